// round 6
// baseline (speedup 1.0000x reference)
#include <cuda_runtime.h>
#include <math.h>

#define NN 8192
#define DD 512

// Scratch (static device globals — no runtime allocation allowed)
__device__ float g_featn[(size_t)NN * DD];          // normalized features, 16 MB
__device__ float g_adj[(size_t)NN * NN];            // dense adjacency, 256 MB
__device__ float g_pos[(size_t)NN * 2];
__device__ float g_lam, g_one_m_lam, g_temp;        // exp-form (output values)
__device__ float g_lam_key, g_oml_key;              // XLA tanh-form (ranking keys)

// Fast sigmoid for output values (value-level diffs vs ref are ulp-scale).
__device__ __forceinline__ float sigmoid_f(float x) {
    if (x >= 0.0f) {
        float e = expf(-x);
        return __fdiv_rn(1.0f, __fadd_rn(1.0f, e));
    } else {
        float e = expf(x);
        return __fdiv_rn(e, __fadd_rn(1.0f, e));
    }
}

// ---------------------------------------------------------------------------
// Bitwise replica of XLA's f32 tanh (xla/service/llvm_ir/math_ops.cc,
// EmitFastTanh): clamp to +-7.90531110763549805, rational p(x2)/q(x2) in
// fma chain, passthrough for |x| < 0.0004.
// ---------------------------------------------------------------------------
__device__ __forceinline__ float xla_tanh_f32(float x) {
    const float kClamp = 7.90531110763549805f;
    float xc = fminf(fmaxf(x, -kClamp), kClamp);
    float x2 = __fmul_rn(xc, xc);
    float p = __fmaf_rn(x2, -2.76076847742355e-16f, 2.00018790482477e-13f);
    p = __fmaf_rn(x2, p, -8.60467152213735e-11f);
    p = __fmaf_rn(x2, p, 5.12229709037114e-08f);
    p = __fmaf_rn(x2, p, 1.48572235717979e-05f);
    p = __fmaf_rn(x2, p, 6.37261928875436e-04f);
    p = __fmaf_rn(x2, p, 4.89352455891786e-03f);
    float num = __fmul_rn(xc, p);
    float q = __fmaf_rn(x2, 1.19825839466702e-06f, 1.18534705686654e-04f);
    q = __fmaf_rn(x2, q, 2.26843463243900e-03f);
    q = __fmaf_rn(x2, q, 4.89352518554385e-03f);
    float r = __fdiv_rn(num, q);
    return (fabsf(x) < 0.0004f) ? x : r;
}

// XLA logistic_expander: logistic(x) = 0.5 + 0.5 * tanh(0.5 * x)
__device__ __forceinline__ float xla_logistic_f32(float x) {
    float t = xla_tanh_f32(__fmul_rn(0.5f, x));
    return __fadd_rn(0.5f, __fmul_rn(0.5f, t));
}

// Reference-replica adjacency value for ranking: exact fp32 elementwise ops,
// correctly-rounded expf (glibc-style, via fp64), XLA tanh-form logistic.
__device__ __forceinline__ float ref_adj_key(float simf, int i, int j,
                                             float lamk, float omlk, float temp) {
    float px = g_pos[2 * i], py = g_pos[2 * i + 1];
    float qx = g_pos[2 * j], qy = g_pos[2 * j + 1];
    float sqa = __fadd_rn(__fmul_rn(px, px), __fmul_rn(py, py));
    float sqb = __fadd_rn(__fmul_rn(qx, qx), __fmul_rn(qy, qy));
    float P = __fmaf_rn(py, qy, __fmul_rn(px, qx));
    float S = __fadd_rn(sqa, sqb);
    float d2 = __fadd_rn(S, -(2.0f * P));
    d2 = fmaxf(d2, 0.0f);
    float arg = -__fdiv_rn(d2, 5000.0f);
    float sp = (float)exp((double)arg);     // correctly-rounded fp32 exp
    float comb = __fadd_rn(__fmul_rn(lamk, simf), __fmul_rn(omlk, sp));
    float z = __fmul_rn(comb, temp);
    return xla_logistic_f32(z);
}

// ---------------------------------------------------------------------------
// Kernel 1: row-normalize (F.normalize, eps=1e-12); norm in fp64.
// ---------------------------------------------------------------------------
__global__ void prep_kernel(const float* __restrict__ feat,
                            const float* __restrict__ pos,
                            const float* __restrict__ lamw,
                            const float* __restrict__ temp) {
    int row = blockIdx.x;
    int tid = threadIdx.x;
    __shared__ double red[256];

    double ss = 0.0;
    for (int j = tid; j < DD; j += 256) {
        double v = (double)feat[(size_t)row * DD + j];
        ss += v * v;
    }
    red[tid] = ss;
    __syncthreads();
    for (int s = 128; s > 0; s >>= 1) {
        if (tid < s) red[tid] += red[tid + s];
        __syncthreads();
    }
    float nrm = (float)sqrt(red[0]);
    nrm = fmaxf(nrm, 1e-12f);
    for (int j = tid; j < DD; j += 256) {
        g_featn[(size_t)row * DD + j] = __fdiv_rn(feat[(size_t)row * DD + j], nrm);
    }
    if (tid < 2) g_pos[2 * row + tid] = pos[2 * row + tid];
    if (row == 0 && tid == 0) {
        float lam = sigmoid_f(*lamw);
        g_lam = lam;
        g_one_m_lam = 1.0f - lam;
        g_temp = *temp;
        float lamk = xla_logistic_f32(*lamw);   // reference's lam
        g_lam_key = lamk;
        g_oml_key = __fadd_rn(1.0f, -lamk);
    }
}

// ---------------------------------------------------------------------------
// Kernel 2: fused GEMM + spatial + sigmoid -> g_adj
// 128x128 tile per CTA, BK=8, 256 threads, 8x8 micro-tile.
// ---------------------------------------------------------------------------
#define BM 128
#define BN 128
#define BK 8

__global__ __launch_bounds__(256, 2)
void adj_gemm_kernel(const float* __restrict__ pos) {
    __shared__ float As[BK][BM];
    __shared__ float Bs[BK][BN];

    const int tid = threadIdx.x;
    const int tn = tid & 15;
    const int tm = tid >> 4;
    const int m0 = blockIdx.y * BM;
    const int n0 = blockIdx.x * BN;

    const int lrow = tid >> 1;
    const int lk   = (tid & 1) * 4;

    float acc[8][8];
#pragma unroll
    for (int i = 0; i < 8; i++)
#pragma unroll
        for (int j = 0; j < 8; j++) acc[i][j] = 0.0f;

    for (int k0 = 0; k0 < DD; k0 += BK) {
        float4 a = *(const float4*)&g_featn[(size_t)(m0 + lrow) * DD + k0 + lk];
        float4 b = *(const float4*)&g_featn[(size_t)(n0 + lrow) * DD + k0 + lk];
        __syncthreads();
        As[lk + 0][lrow] = a.x; As[lk + 1][lrow] = a.y;
        As[lk + 2][lrow] = a.z; As[lk + 3][lrow] = a.w;
        Bs[lk + 0][lrow] = b.x; Bs[lk + 1][lrow] = b.y;
        Bs[lk + 2][lrow] = b.z; Bs[lk + 3][lrow] = b.w;
        __syncthreads();

#pragma unroll
        for (int kk = 0; kk < BK; kk++) {
            float ra[8], rb[8];
            float4 ra0 = *(const float4*)&As[kk][tm * 8];
            float4 ra1 = *(const float4*)&As[kk][tm * 8 + 4];
            float4 rb0 = *(const float4*)&Bs[kk][tn * 8];
            float4 rb1 = *(const float4*)&Bs[kk][tn * 8 + 4];
            ra[0] = ra0.x; ra[1] = ra0.y; ra[2] = ra0.z; ra[3] = ra0.w;
            ra[4] = ra1.x; ra[5] = ra1.y; ra[6] = ra1.z; ra[7] = ra1.w;
            rb[0] = rb0.x; rb[1] = rb0.y; rb[2] = rb0.z; rb[3] = rb0.w;
            rb[4] = rb1.x; rb[5] = rb1.y; rb[6] = rb1.z; rb[7] = rb1.w;
#pragma unroll
            for (int i = 0; i < 8; i++)
#pragma unroll
                for (int j = 0; j < 8; j++)
                    acc[i][j] = fmaf(ra[i], rb[j], acc[i][j]);
        }
    }

    const float lam = g_lam, oml = g_one_m_lam, temp = g_temp;

    float px[8], py[8], sqa[8], qx[8], qy[8], sqb[8];
#pragma unroll
    for (int i = 0; i < 8; i++) {
        int m = m0 + tm * 8 + i;
        px[i] = pos[2 * m];
        py[i] = pos[2 * m + 1];
        sqa[i] = __fadd_rn(__fmul_rn(px[i], px[i]), __fmul_rn(py[i], py[i]));
    }
#pragma unroll
    for (int j = 0; j < 8; j++) {
        int n = n0 + tn * 8 + j;
        qx[j] = pos[2 * n];
        qy[j] = pos[2 * n + 1];
        sqb[j] = __fadd_rn(__fmul_rn(qx[j], qx[j]), __fmul_rn(qy[j], qy[j]));
    }

#pragma unroll
    for (int i = 0; i < 8; i++) {
        int m = m0 + tm * 8 + i;
        float o[8];
#pragma unroll
        for (int j = 0; j < 8; j++) {
            float P = __fmaf_rn(py[i], qy[j], __fmul_rn(px[i], qx[j]));
            float S = __fadd_rn(sqa[i], sqb[j]);
            float d2 = __fadd_rn(S, -(2.0f * P));
            d2 = fmaxf(d2, 0.0f);
            float sp = expf(-__fdiv_rn(d2, 5000.0f));
            float comb = __fadd_rn(__fmul_rn(lam, acc[i][j]),
                                   __fmul_rn(oml, sp));
            float arg = __fmul_rn(comb, temp);
            o[j] = sigmoid_f(arg);
        }
        float* dst = &g_adj[(size_t)m * NN + n0 + tn * 8];
        *(float4*)(dst)     = make_float4(o[0], o[1], o[2], o[3]);
        *(float4*)(dst + 4) = make_float4(o[4], o[5], o[6], o[7]);
    }
}

// ---------------------------------------------------------------------------
// Kernel 3: per-row exact top-k + boundary-band refinement with
// reference-replica keys (XLA-CPU pipeline: CR sim, CR exp, tanh-logistic).
// Exact key ties -> lowest index (lax.top_k stability).
// ---------------------------------------------------------------------------
#define TAU 2e-5f
#define MAXBAND 128

__global__ void topk_kernel(float* __restrict__ out,
                            const int* __restrict__ kptr,
                            long long out_size) {
    const int row = blockIdx.x;
    const int tid = threadIdx.x;
    const int NT = 256;

    __shared__ int cnt[256];
    __shared__ unsigned int sh_pfx;
    __shared__ int sh_rem;
    __shared__ int sh_nabove, sh_bandcnt;
    __shared__ int bandidx[MAXBAND];
    __shared__ unsigned int bandkey[MAXBAND];
    __shared__ unsigned char bandkeep[MAXBAND];
    __shared__ double red_d[256];
    extern __shared__ unsigned int srow[];   // NN uint32

    const int k = *kptr;
    const unsigned int* arow =
        (const unsigned int*)(g_adj + (size_t)row * NN);
    for (int j = tid; j < NN; j += NT) srow[j] = arow[j];
    if (tid == 0) { sh_pfx = 0u; sh_rem = k; sh_nabove = 0; sh_bandcnt = 0; }
    __syncthreads();

    // 4-pass MSB radix select for the k-th largest key (values in (0,1):
    // positive floats => uint order == float order).
#pragma unroll 1
    for (int pass = 0; pass < 4; pass++) {
        int shift = 24 - 8 * pass;
        unsigned int hi_mask = (pass == 0) ? 0u : (0xFFFFFFFFu << (shift + 8));
        cnt[tid] = 0;
        __syncthreads();
        unsigned int pfx = sh_pfx;
        for (int j = tid; j < NN; j += NT) {
            unsigned int v = srow[j];
            if ((v & hi_mask) == pfx)
                atomicAdd(&cnt[(v >> shift) & 255], 1);
        }
        __syncthreads();
        if (tid == 0) {
            int rem = sh_rem;
            int b = 255;
            for (; b > 0; b--) {
                if (rem - cnt[b] <= 0) break;
                rem -= cnt[b];
            }
            sh_pfx = pfx | ((unsigned int)b << shift);
            sh_rem = rem;
        }
        __syncthreads();
    }

    const float Tf = __uint_as_float(sh_pfx);
    const float band_hi = Tf + TAU;
    const float band_lo = Tf - TAU;

    for (int j = tid; j < NN; j += NT) {
        float v = __uint_as_float(srow[j]);
        if (v > band_hi) {
            atomicAdd(&sh_nabove, 1);
        } else if (v >= band_lo) {
            int p = atomicAdd(&sh_bandcnt, 1);
            if (p < MAXBAND) bandidx[p] = j;
        }
    }
    __syncthreads();

    const int n_above = sh_nabove;
    const int band_cnt_raw = sh_bandcnt;
    const int band_cnt = min(band_cnt_raw, MAXBAND);
    const int need = k - n_above;     // >= 1 always

    bool refined = false;
    if (band_cnt_raw <= MAXBAND && band_cnt_raw > need) {
        refined = true;
        const float lamk = g_lam_key, omlk = g_oml_key, temp = g_temp;
        const float* fa = &g_featn[(size_t)row * DD];

        for (int c = 0; c < band_cnt; c++) {
            int j = bandidx[c];
            const float* fb = &g_featn[(size_t)j * DD];
            double part = 0.0;
            for (int t = tid; t < DD; t += NT)
                part += (double)fa[t] * (double)fb[t];
            red_d[tid] = part;
            __syncthreads();
            for (int s = 128; s > 0; s >>= 1) {
                if (tid < s) red_d[tid] += red_d[tid + s];
                __syncthreads();
            }
            if (tid == 0) {
                float simf = (float)red_d[0];   // correctly-rounded fp32 sim
                float a = ref_adj_key(simf, row, j, lamk, omlk, temp);
                bandkey[c] = __float_as_uint(a);
                bandkeep[c] = 0;
            }
            __syncthreads();
        }
        // Pick top `need` by (key desc, index asc); exact ties -> lowest idx.
        if (tid == 0) {
            for (int pick = 0; pick < need; pick++) {
                int best = -1;
                for (int c = 0; c < band_cnt; c++) {
                    if (bandkeep[c]) continue;
                    if (best < 0 ||
                        bandkey[c] > bandkey[best] ||
                        (bandkey[c] == bandkey[best] && bandidx[c] < bandidx[best]))
                        best = c;
                }
                bandkeep[best] = 1;
            }
        }
        __syncthreads();
    }

    // Write masked output.
    float* orow = out + (size_t)row * NN;
    const unsigned int Tkey = sh_pfx;
    for (int j = tid; j < NN; j += NT) {
        unsigned int vb = srow[j];
        float v = __uint_as_float(vb);
        float o = 0.0f;
        if (v > band_hi) {
            o = v;
        } else if (v >= band_lo) {
            if (!refined) {
                if (band_cnt_raw <= MAXBAND) {
                    o = v;                       // band_cnt == need: keep all
                } else {
                    o = (vb >= Tkey) ? v : 0.0f; // overflow fallback
                }
            } else {
                for (int c = 0; c < band_cnt; c++) {
                    if (bandidx[c] == j) { o = bandkeep[c] ? v : 0.0f; break; }
                }
            }
        }
        orow[j] = o;
    }

    if (row == 0 && tid == 0 && out_size > (long long)NN * NN)
        out[(size_t)NN * NN] = g_lam;    // second tuple output: lam scalar
}

// ---------------------------------------------------------------------------
extern "C" void kernel_launch(void* const* d_in, const int* in_sizes, int n_in,
                              void* d_out, int out_size) {
    const float* feat = (const float*)d_in[0];   // (8192, 512)
    const float* pos  = (const float*)d_in[1];   // (8192, 2)
    const float* lamw = (const float*)d_in[2];   // scalar
    const float* temp = (const float*)d_in[3];   // scalar
    const int*   kptr = (const int*)d_in[4];     // scalar int
    float* out = (float*)d_out;

    prep_kernel<<<NN, 256>>>(feat, pos, lamw, temp);
    adj_gemm_kernel<<<dim3(NN / BN, NN / BM), 256>>>(pos);
    topk_kernel<<<NN, 256, NN * sizeof(unsigned int)>>>(out, kptr,
                                                        (long long)out_size);
}

// round 7
// speedup vs baseline: 1.6215x; 1.6215x over previous
#include <cuda_runtime.h>
#include <math.h>

#define NN 8192
#define DD 512

// Scratch (static device globals — no runtime allocation allowed)
__device__ float g_featn[(size_t)NN * DD];          // normalized features, 16 MB
__device__ float g_pos[(size_t)NN * 2];
__device__ float g_lam, g_one_m_lam, g_temp;        // exp-form (output values)
__device__ float g_lam_key, g_oml_key;              // XLA tanh-form (ranking keys)

// Fast sigmoid for output values (value-level diffs vs ref are ulp-scale).
__device__ __forceinline__ float sigmoid_f(float x) {
    if (x >= 0.0f) {
        float e = expf(-x);
        return __fdiv_rn(1.0f, __fadd_rn(1.0f, e));
    } else {
        float e = expf(x);
        return __fdiv_rn(e, __fadd_rn(1.0f, e));
    }
}

// ---------------------------------------------------------------------------
// Bitwise replica of XLA's f32 tanh (EmitFastTanh) — validated round 6.
// ---------------------------------------------------------------------------
__device__ __forceinline__ float xla_tanh_f32(float x) {
    const float kClamp = 7.90531110763549805f;
    float xc = fminf(fmaxf(x, -kClamp), kClamp);
    float x2 = __fmul_rn(xc, xc);
    float p = __fmaf_rn(x2, -2.76076847742355e-16f, 2.00018790482477e-13f);
    p = __fmaf_rn(x2, p, -8.60467152213735e-11f);
    p = __fmaf_rn(x2, p, 5.12229709037114e-08f);
    p = __fmaf_rn(x2, p, 1.48572235717979e-05f);
    p = __fmaf_rn(x2, p, 6.37261928875436e-04f);
    p = __fmaf_rn(x2, p, 4.89352455891786e-03f);
    float num = __fmul_rn(xc, p);
    float q = __fmaf_rn(x2, 1.19825839466702e-06f, 1.18534705686654e-04f);
    q = __fmaf_rn(x2, q, 2.26843463243900e-03f);
    q = __fmaf_rn(x2, q, 4.89352518554385e-03f);
    float r = __fdiv_rn(num, q);
    return (fabsf(x) < 0.0004f) ? x : r;
}

// XLA logistic_expander: logistic(x) = 0.5 + 0.5 * tanh(0.5 * x)
__device__ __forceinline__ float xla_logistic_f32(float x) {
    float t = xla_tanh_f32(__fmul_rn(0.5f, x));
    return __fadd_rn(0.5f, __fmul_rn(0.5f, t));
}

// Reference-replica adjacency value for ranking — validated round 6.
__device__ __forceinline__ float ref_adj_key(float simf, int i, int j,
                                             float lamk, float omlk, float temp) {
    float px = g_pos[2 * i], py = g_pos[2 * i + 1];
    float qx = g_pos[2 * j], qy = g_pos[2 * j + 1];
    float sqa = __fadd_rn(__fmul_rn(px, px), __fmul_rn(py, py));
    float sqb = __fadd_rn(__fmul_rn(qx, qx), __fmul_rn(qy, qy));
    float P = __fmaf_rn(py, qy, __fmul_rn(px, qx));
    float S = __fadd_rn(sqa, sqb);
    float d2 = __fadd_rn(S, -(2.0f * P));
    d2 = fmaxf(d2, 0.0f);
    float arg = -__fdiv_rn(d2, 5000.0f);
    float sp = (float)exp((double)arg);     // correctly-rounded fp32 exp
    float comb = __fadd_rn(__fmul_rn(lamk, simf), __fmul_rn(omlk, sp));
    float z = __fmul_rn(comb, temp);
    return xla_logistic_f32(z);
}

// ---------------------------------------------------------------------------
// Kernel 1: row-normalize, warp-per-row (8 rows/CTA), fp64 norm via shuffles.
// ---------------------------------------------------------------------------
__global__ void prep_kernel(const float* __restrict__ feat,
                            const float* __restrict__ pos,
                            const float* __restrict__ lamw,
                            const float* __restrict__ temp) {
    int gwarp = (blockIdx.x * blockDim.x + threadIdx.x) >> 5;
    int lane = threadIdx.x & 31;
    if (gwarp >= NN) return;
    const float* src = feat + (size_t)gwarp * DD;

    double ss = 0.0;
#pragma unroll
    for (int j = lane; j < DD; j += 32) {
        double v = (double)src[j];
        ss += v * v;
    }
#pragma unroll
    for (int off = 16; off > 0; off >>= 1)
        ss += __shfl_down_sync(0xFFFFFFFFu, ss, off);
    ss = __shfl_sync(0xFFFFFFFFu, ss, 0);

    float nrm = fmaxf((float)sqrt(ss), 1e-12f);
    float* dst = g_featn + (size_t)gwarp * DD;
#pragma unroll
    for (int j = lane; j < DD; j += 32)
        dst[j] = __fdiv_rn(src[j], nrm);

    if (lane < 2) g_pos[2 * gwarp + lane] = pos[2 * gwarp + lane];
    if (gwarp == 0 && lane == 0) {
        float lam = sigmoid_f(*lamw);
        g_lam = lam;
        g_one_m_lam = 1.0f - lam;
        g_temp = *temp;
        float lamk = xla_logistic_f32(*lamw);   // reference's lam
        g_lam_key = lamk;
        g_oml_key = __fadd_rn(1.0f, -lamk);
    }
}

// ---------------------------------------------------------------------------
// Kernel 2: fused GEMM + spatial + sigmoid, SYMMETRIC: only upper-triangle
// 128x128 tiles (2080 of 4096); off-diagonal tiles stored twice (normal +
// transposed). Mirrored values are bitwise identical (fma commutative in
// a*b, epilogue symmetric in (i,j)) -> numerics unchanged vs round 6.
// Writes adjacency directly into the output buffer.
// ---------------------------------------------------------------------------
#define BM 128
#define BN 128
#define BK 8
#define NTILE (NN / BM)                    // 64
#define NPAIRS (NTILE * (NTILE + 1) / 2)   // 2080

__global__ __launch_bounds__(256, 2)
void adj_gemm_kernel(const float* __restrict__ pos, float* __restrict__ outp) {
    __shared__ float As[BK][BM];
    __shared__ float Bs[BK][BN];

    // decode linear tile id -> (bi, bj), bj >= bi
    int t = blockIdx.x;
    int bi = (int)((2.0 * NTILE + 1.0 -
                    sqrt((2.0 * NTILE + 1.0) * (2.0 * NTILE + 1.0) - 8.0 * (double)t)) * 0.5);
    while ((bi + 1) * NTILE - ((bi + 1) * bi) / 2 <= t) bi++;
    while (bi * NTILE - (bi * (bi - 1)) / 2 > t) bi--;
    int bj = bi + (t - (bi * NTILE - (bi * (bi - 1)) / 2));

    const int tid = threadIdx.x;
    const int tn = tid & 15;
    const int tm = tid >> 4;
    const int m0 = bi * BM;
    const int n0 = bj * BN;

    const int lrow = tid >> 1;
    const int lk   = (tid & 1) * 4;

    float acc[8][8];
#pragma unroll
    for (int i = 0; i < 8; i++)
#pragma unroll
        for (int j = 0; j < 8; j++) acc[i][j] = 0.0f;

    for (int k0 = 0; k0 < DD; k0 += BK) {
        float4 a = *(const float4*)&g_featn[(size_t)(m0 + lrow) * DD + k0 + lk];
        float4 b = *(const float4*)&g_featn[(size_t)(n0 + lrow) * DD + k0 + lk];
        __syncthreads();
        As[lk + 0][lrow] = a.x; As[lk + 1][lrow] = a.y;
        As[lk + 2][lrow] = a.z; As[lk + 3][lrow] = a.w;
        Bs[lk + 0][lrow] = b.x; Bs[lk + 1][lrow] = b.y;
        Bs[lk + 2][lrow] = b.z; Bs[lk + 3][lrow] = b.w;
        __syncthreads();

#pragma unroll
        for (int kk = 0; kk < BK; kk++) {
            float ra[8], rb[8];
            float4 ra0 = *(const float4*)&As[kk][tm * 8];
            float4 ra1 = *(const float4*)&As[kk][tm * 8 + 4];
            float4 rb0 = *(const float4*)&Bs[kk][tn * 8];
            float4 rb1 = *(const float4*)&Bs[kk][tn * 8 + 4];
            ra[0] = ra0.x; ra[1] = ra0.y; ra[2] = ra0.z; ra[3] = ra0.w;
            ra[4] = ra1.x; ra[5] = ra1.y; ra[6] = ra1.z; ra[7] = ra1.w;
            rb[0] = rb0.x; rb[1] = rb0.y; rb[2] = rb0.z; rb[3] = rb0.w;
            rb[4] = rb1.x; rb[5] = rb1.y; rb[6] = rb1.z; rb[7] = rb1.w;
#pragma unroll
            for (int i = 0; i < 8; i++)
#pragma unroll
                for (int j = 0; j < 8; j++)
                    acc[i][j] = fmaf(ra[i], rb[j], acc[i][j]);
        }
    }

    // ---- epilogue (same fp ops as round 6), result in-place into acc ----
    const float lam = g_lam, oml = g_one_m_lam, temp = g_temp;

    float px[8], py[8], sqa[8], qx[8], qy[8], sqb[8];
#pragma unroll
    for (int i = 0; i < 8; i++) {
        int m = m0 + tm * 8 + i;
        px[i] = pos[2 * m];
        py[i] = pos[2 * m + 1];
        sqa[i] = __fadd_rn(__fmul_rn(px[i], px[i]), __fmul_rn(py[i], py[i]));
    }
#pragma unroll
    for (int j = 0; j < 8; j++) {
        int n = n0 + tn * 8 + j;
        qx[j] = pos[2 * n];
        qy[j] = pos[2 * n + 1];
        sqb[j] = __fadd_rn(__fmul_rn(qx[j], qx[j]), __fmul_rn(qy[j], qy[j]));
    }

#pragma unroll
    for (int i = 0; i < 8; i++) {
#pragma unroll
        for (int j = 0; j < 8; j++) {
            float P = __fmaf_rn(py[i], qy[j], __fmul_rn(px[i], qx[j]));
            float S = __fadd_rn(sqa[i], sqb[j]);
            float d2 = __fadd_rn(S, -(2.0f * P));
            d2 = fmaxf(d2, 0.0f);
            float sp = expf(-__fdiv_rn(d2, 5000.0f));
            float comb = __fadd_rn(__fmul_rn(lam, acc[i][j]),
                                   __fmul_rn(oml, sp));
            float arg = __fmul_rn(comb, temp);
            acc[i][j] = sigmoid_f(arg);
        }
    }

    // normal block store
#pragma unroll
    for (int i = 0; i < 8; i++) {
        int m = m0 + tm * 8 + i;
        float* dst = &outp[(size_t)m * NN + n0 + tn * 8];
        *(float4*)(dst)     = make_float4(acc[i][0], acc[i][1], acc[i][2], acc[i][3]);
        *(float4*)(dst + 4) = make_float4(acc[i][4], acc[i][5], acc[i][6], acc[i][7]);
    }

    // mirrored block store (bitwise-identical values, transposed layout)
    if (bi != bj) {
#pragma unroll
        for (int j = 0; j < 8; j++) {
            int n = n0 + tn * 8 + j;
            float* dst = &outp[(size_t)n * NN + m0 + tm * 8];
            *(float4*)(dst)     = make_float4(acc[0][j], acc[1][j], acc[2][j], acc[3][j]);
            *(float4*)(dst + 4) = make_float4(acc[4][j], acc[5][j], acc[6][j], acc[7][j]);
        }
    }
}

// ---------------------------------------------------------------------------
// Kernel 3: per-row exact top-k IN PLACE on the output buffer + boundary-band
// refinement with reference-replica keys (validated round 6, unchanged logic).
// ---------------------------------------------------------------------------
#define TAU 2e-5f
#define MAXBAND 128

__global__ void topk_kernel(float* __restrict__ out,
                            const int* __restrict__ kptr,
                            long long out_size) {
    const int row = blockIdx.x;
    const int tid = threadIdx.x;
    const int NT = 256;

    __shared__ int cnt[256];
    __shared__ unsigned int sh_pfx;
    __shared__ int sh_rem;
    __shared__ int sh_nabove, sh_bandcnt;
    __shared__ int bandidx[MAXBAND];
    __shared__ unsigned int bandkey[MAXBAND];
    __shared__ unsigned char bandkeep[MAXBAND];
    __shared__ double red_d[256];
    extern __shared__ unsigned int srow[];   // NN uint32

    const int k = *kptr;
    const unsigned int* arow =
        (const unsigned int*)(out + (size_t)row * NN);
    for (int j = tid; j < NN; j += NT) srow[j] = arow[j];
    if (tid == 0) { sh_pfx = 0u; sh_rem = k; sh_nabove = 0; sh_bandcnt = 0; }
    __syncthreads();

    // 4-pass MSB radix select for the k-th largest key (values in (0,1):
    // positive floats => uint order == float order).
#pragma unroll 1
    for (int pass = 0; pass < 4; pass++) {
        int shift = 24 - 8 * pass;
        unsigned int hi_mask = (pass == 0) ? 0u : (0xFFFFFFFFu << (shift + 8));
        cnt[tid] = 0;
        __syncthreads();
        unsigned int pfx = sh_pfx;
        for (int j = tid; j < NN; j += NT) {
            unsigned int v = srow[j];
            if ((v & hi_mask) == pfx)
                atomicAdd(&cnt[(v >> shift) & 255], 1);
        }
        __syncthreads();
        if (tid == 0) {
            int rem = sh_rem;
            int b = 255;
            for (; b > 0; b--) {
                if (rem - cnt[b] <= 0) break;
                rem -= cnt[b];
            }
            sh_pfx = pfx | ((unsigned int)b << shift);
            sh_rem = rem;
        }
        __syncthreads();
    }

    const float Tf = __uint_as_float(sh_pfx);
    const float band_hi = Tf + TAU;
    const float band_lo = Tf - TAU;

    for (int j = tid; j < NN; j += NT) {
        float v = __uint_as_float(srow[j]);
        if (v > band_hi) {
            atomicAdd(&sh_nabove, 1);
        } else if (v >= band_lo) {
            int p = atomicAdd(&sh_bandcnt, 1);
            if (p < MAXBAND) bandidx[p] = j;
        }
    }
    __syncthreads();

    const int n_above = sh_nabove;
    const int band_cnt_raw = sh_bandcnt;
    const int band_cnt = min(band_cnt_raw, MAXBAND);
    const int need = k - n_above;     // >= 1 always

    bool refined = false;
    if (band_cnt_raw <= MAXBAND && band_cnt_raw > need) {
        refined = true;
        const float lamk = g_lam_key, omlk = g_oml_key, temp = g_temp;
        const float* fa = &g_featn[(size_t)row * DD];

        for (int c = 0; c < band_cnt; c++) {
            int j = bandidx[c];
            const float* fb = &g_featn[(size_t)j * DD];
            double part = 0.0;
            for (int t = tid; t < DD; t += NT)
                part += (double)fa[t] * (double)fb[t];
            red_d[tid] = part;
            __syncthreads();
            for (int s = 128; s > 0; s >>= 1) {
                if (tid < s) red_d[tid] += red_d[tid + s];
                __syncthreads();
            }
            if (tid == 0) {
                float simf = (float)red_d[0];   // correctly-rounded fp32 sim
                float a = ref_adj_key(simf, row, j, lamk, omlk, temp);
                bandkey[c] = __float_as_uint(a);
                bandkeep[c] = 0;
            }
            __syncthreads();
        }
        // Pick top `need` by (key desc, index asc); exact ties -> lowest idx.
        if (tid == 0) {
            for (int pick = 0; pick < need; pick++) {
                int best = -1;
                for (int c = 0; c < band_cnt; c++) {
                    if (bandkeep[c]) continue;
                    if (best < 0 ||
                        bandkey[c] > bandkey[best] ||
                        (bandkey[c] == bandkey[best] && bandidx[c] < bandidx[best]))
                        best = c;
                }
                bandkeep[best] = 1;
            }
        }
        __syncthreads();
    }

    // Write masked output (in place).
    float* orow = out + (size_t)row * NN;
    const unsigned int Tkey = sh_pfx;
    for (int j = tid; j < NN; j += NT) {
        unsigned int vb = srow[j];
        float v = __uint_as_float(vb);
        float o = 0.0f;
        if (v > band_hi) {
            o = v;
        } else if (v >= band_lo) {
            if (!refined) {
                if (band_cnt_raw <= MAXBAND) {
                    o = v;                       // band_cnt == need: keep all
                } else {
                    o = (vb >= Tkey) ? v : 0.0f; // overflow fallback
                }
            } else {
                for (int c = 0; c < band_cnt; c++) {
                    if (bandidx[c] == j) { o = bandkeep[c] ? v : 0.0f; break; }
                }
            }
        }
        orow[j] = o;
    }

    if (row == 0 && tid == 0 && out_size > (long long)NN * NN)
        out[(size_t)NN * NN] = g_lam;    // second tuple output: lam scalar
}

// ---------------------------------------------------------------------------
extern "C" void kernel_launch(void* const* d_in, const int* in_sizes, int n_in,
                              void* d_out, int out_size) {
    const float* feat = (const float*)d_in[0];   // (8192, 512)
    const float* pos  = (const float*)d_in[1];   // (8192, 2)
    const float* lamw = (const float*)d_in[2];   // scalar
    const float* temp = (const float*)d_in[3];   // scalar
    const int*   kptr = (const int*)d_in[4];     // scalar int
    float* out = (float*)d_out;

    prep_kernel<<<NN / 8, 256>>>(feat, pos, lamw, temp);
    adj_gemm_kernel<<<NPAIRS, 256>>>(pos, out);
    topk_kernel<<<NN, 256, NN * sizeof(unsigned int)>>>(out, kptr,
                                                        (long long)out_size);
}

// round 9
// speedup vs baseline: 1.6585x; 1.0228x over previous
#include <cuda_runtime.h>
#include <cuda_bf16.h>
#include <math.h>

#define NN 8192
#define DD 512

// Scratch (static device globals — no runtime allocation allowed)
__device__ float g_featn[(size_t)NN * DD];                     // normalized feats
__device__ __align__(16) __nv_bfloat16 g_sp0[(size_t)NN * DD]; // bf16 split hi
__device__ __align__(16) __nv_bfloat16 g_sp1[(size_t)NN * DD]; // bf16 split lo
__device__ float g_pos[(size_t)NN * 2];
__device__ float g_lam, g_one_m_lam, g_temp;        // exp-form (output values)
__device__ float g_lam_key, g_oml_key;              // XLA tanh-form (ranking keys)

// m16n8k16 bf16 MMA, fp32 accumulate (plain PTX, valid on sm_103)
#define MMA16816(d, a, b)                                                     \
    asm volatile(                                                             \
        "mma.sync.aligned.m16n8k16.row.col.f32.bf16.bf16.f32 "                \
        "{%0,%1,%2,%3}, {%4,%5,%6,%7}, {%8,%9}, {%0,%1,%2,%3};"               \
        : "+f"((d)[0]), "+f"((d)[1]), "+f"((d)[2]), "+f"((d)[3])              \
        : "r"((a)[0]), "r"((a)[1]), "r"((a)[2]), "r"((a)[3]),                 \
          "r"((b)[0]), "r"((b)[1]))

// ---------------------------------------------------------------------------
// Numerics helpers (validated rounds 1-6 — DO NOT CHANGE)
// ---------------------------------------------------------------------------
__device__ __forceinline__ float sigmoid_f(float x) {
    if (x >= 0.0f) {
        float e = expf(-x);
        return __fdiv_rn(1.0f, __fadd_rn(1.0f, e));
    } else {
        float e = expf(x);
        return __fdiv_rn(e, __fadd_rn(1.0f, e));
    }
}

__device__ __forceinline__ float xla_tanh_f32(float x) {
    const float kClamp = 7.90531110763549805f;
    float xc = fminf(fmaxf(x, -kClamp), kClamp);
    float x2 = __fmul_rn(xc, xc);
    float p = __fmaf_rn(x2, -2.76076847742355e-16f, 2.00018790482477e-13f);
    p = __fmaf_rn(x2, p, -8.60467152213735e-11f);
    p = __fmaf_rn(x2, p, 5.12229709037114e-08f);
    p = __fmaf_rn(x2, p, 1.48572235717979e-05f);
    p = __fmaf_rn(x2, p, 6.37261928875436e-04f);
    p = __fmaf_rn(x2, p, 4.89352455891786e-03f);
    float num = __fmul_rn(xc, p);
    float q = __fmaf_rn(x2, 1.19825839466702e-06f, 1.18534705686654e-04f);
    q = __fmaf_rn(x2, q, 2.26843463243900e-03f);
    q = __fmaf_rn(x2, q, 4.89352518554385e-03f);
    float r = __fdiv_rn(num, q);
    return (fabsf(x) < 0.0004f) ? x : r;
}

__device__ __forceinline__ float xla_logistic_f32(float x) {
    float t = xla_tanh_f32(__fmul_rn(0.5f, x));
    return __fadd_rn(0.5f, __fmul_rn(0.5f, t));
}

__device__ __forceinline__ float ref_adj_key(float simf, int i, int j,
                                             float lamk, float omlk, float temp) {
    float px = g_pos[2 * i], py = g_pos[2 * i + 1];
    float qx = g_pos[2 * j], qy = g_pos[2 * j + 1];
    float sqa = __fadd_rn(__fmul_rn(px, px), __fmul_rn(py, py));
    float sqb = __fadd_rn(__fmul_rn(qx, qx), __fmul_rn(qy, qy));
    float P = __fmaf_rn(py, qy, __fmul_rn(px, qx));
    float S = __fadd_rn(sqa, sqb);
    float d2 = __fadd_rn(S, -(2.0f * P));
    d2 = fmaxf(d2, 0.0f);
    float arg = -__fdiv_rn(d2, 5000.0f);
    float sp = (float)exp((double)arg);     // correctly-rounded fp32 exp
    float comb = __fadd_rn(__fmul_rn(lamk, simf), __fmul_rn(omlk, sp));
    float z = __fmul_rn(comb, temp);
    return xla_logistic_f32(z);
}

// ---------------------------------------------------------------------------
// Kernel 1: row-normalize (fp64 norm) + 2-way bf16 split of normalized feats.
// ---------------------------------------------------------------------------
__global__ void prep_kernel(const float* __restrict__ feat,
                            const float* __restrict__ pos,
                            const float* __restrict__ lamw,
                            const float* __restrict__ temp) {
    int gwarp = (blockIdx.x * blockDim.x + threadIdx.x) >> 5;
    int lane = threadIdx.x & 31;
    if (gwarp >= NN) return;
    const float* src = feat + (size_t)gwarp * DD;

    double ss = 0.0;
#pragma unroll
    for (int j = lane; j < DD; j += 32) {
        double v = (double)src[j];
        ss += v * v;
    }
#pragma unroll
    for (int off = 16; off > 0; off >>= 1)
        ss += __shfl_down_sync(0xFFFFFFFFu, ss, off);
    ss = __shfl_sync(0xFFFFFFFFu, ss, 0);

    float nrm = fmaxf((float)sqrt(ss), 1e-12f);
    size_t base = (size_t)gwarp * DD;
#pragma unroll
    for (int j = lane; j < DD; j += 32) {
        float v = __fdiv_rn(src[j], nrm);
        g_featn[base + j] = v;
        __nv_bfloat16 b0 = __float2bfloat16_rn(v);
        float r1 = v - __bfloat162float(b0);
        __nv_bfloat16 b1 = __float2bfloat16_rn(r1);
        g_sp0[base + j] = b0;
        g_sp1[base + j] = b1;
    }

    if (lane < 2) g_pos[2 * gwarp + lane] = pos[2 * gwarp + lane];
    if (gwarp == 0 && lane == 0) {
        float lam = sigmoid_f(*lamw);
        g_lam = lam;
        g_one_m_lam = 1.0f - lam;
        g_temp = *temp;
        float lamk = xla_logistic_f32(*lamw);   // reference's lam
        g_lam_key = lamk;
        g_oml_key = __fadd_rn(1.0f, -lamk);
    }
}

// ---------------------------------------------------------------------------
// Kernel 2: mma.sync bf16 2-split GEMM (3 products into one fp32 accumulator)
// + spatial + sigmoid epilogue. Upper-triangle 128x128 tiles; mirrored store
// via padded smem transpose. sim noise ~4e-7 << TAU=2e-5 band.
// ---------------------------------------------------------------------------
#define NTILE (NN / 128)                   // 64
#define NPAIRS (NTILE * (NTILE + 1) / 2)   // 2080
#define EPI_SMEM (128 * 129 * 4)           // 66048 B

__global__ __launch_bounds__(256, 1)
void adj_gemm_mma(const float* __restrict__ pos, float* __restrict__ outp) {
    extern __shared__ float smem_t[];          // 128 x 129
    __shared__ float s_qx[128], s_qy[128], s_sqb[128];

    // decode linear tile id -> (bi, bj), bj >= bi
    int t = blockIdx.x;
    int bi = (int)((2.0 * NTILE + 1.0 -
                    sqrt((2.0 * NTILE + 1.0) * (2.0 * NTILE + 1.0) - 8.0 * (double)t)) * 0.5);
    while ((bi + 1) * NTILE - ((bi + 1) * bi) / 2 <= t) bi++;
    while (bi * NTILE - (bi * (bi - 1)) / 2 > t) bi--;
    int bj = bi + (t - (bi * NTILE - (bi * (bi - 1)) / 2));

    const int m0 = bi * 128, n0 = bj * 128;
    const int tid = threadIdx.x;
    const int wid = tid >> 5;
    const int lane = tid & 31;
    const int gid = lane >> 2;      // group id 0..7
    const int tig = lane & 3;       // thread-in-group

    const int wm = (wid >> 2) * 64;   // warp m-offset in tile (0 or 64)
    const int wn = (wid & 3) * 32;    // warp n-offset in tile (0..96)

    if (tid < 128) {
        int n = n0 + tid;
        float qx = pos[2 * n], qy = pos[2 * n + 1];
        s_qx[tid] = qx; s_qy[tid] = qy;
        s_sqb[tid] = __fadd_rn(__fmul_rn(qx, qx), __fmul_rn(qy, qy));
    }

    // row base element-offsets
    size_t arow[4], brow[4];
#pragma unroll
    for (int mi = 0; mi < 4; mi++)
        arow[mi] = (size_t)(m0 + wm + mi * 16 + gid) * DD;
#pragma unroll
    for (int ni = 0; ni < 4; ni++)
        brow[ni] = (size_t)(n0 + wn + ni * 8 + gid) * DD;

    float d[4][4][4];
#pragma unroll
    for (int mi = 0; mi < 4; mi++)
#pragma unroll
        for (int ni = 0; ni < 4; ni++)
#pragma unroll
            for (int r = 0; r < 4; r++) d[mi][ni][r] = 0.0f;

    const __nv_bfloat16* __restrict__ S0 = g_sp0;
    const __nv_bfloat16* __restrict__ S1 = g_sp1;

#pragma unroll 1
    for (int kk = 0; kk < DD; kk += 16) {
        const int ka = kk + 2 * tig;
        unsigned int a0f[4][4], a1f[4][4], b0f[4][2], b1f[4][2];
#pragma unroll
        for (int mi = 0; mi < 4; mi++) {
            a0f[mi][0] = *(const unsigned int*)(S0 + arow[mi] + ka);
            a0f[mi][1] = *(const unsigned int*)(S0 + arow[mi] + 8 * DD + ka);
            a0f[mi][2] = *(const unsigned int*)(S0 + arow[mi] + ka + 8);
            a0f[mi][3] = *(const unsigned int*)(S0 + arow[mi] + 8 * DD + ka + 8);
            a1f[mi][0] = *(const unsigned int*)(S1 + arow[mi] + ka);
            a1f[mi][1] = *(const unsigned int*)(S1 + arow[mi] + 8 * DD + ka);
            a1f[mi][2] = *(const unsigned int*)(S1 + arow[mi] + ka + 8);
            a1f[mi][3] = *(const unsigned int*)(S1 + arow[mi] + 8 * DD + ka + 8);
        }
#pragma unroll
        for (int ni = 0; ni < 4; ni++) {
            b0f[ni][0] = *(const unsigned int*)(S0 + brow[ni] + ka);
            b0f[ni][1] = *(const unsigned int*)(S0 + brow[ni] + ka + 8);
            b1f[ni][0] = *(const unsigned int*)(S1 + brow[ni] + ka);
            b1f[ni][1] = *(const unsigned int*)(S1 + brow[ni] + ka + 8);
        }
#pragma unroll
        for (int mi = 0; mi < 4; mi++) {
#pragma unroll
            for (int ni = 0; ni < 4; ni++) {
                MMA16816(d[mi][ni], a0f[mi], b0f[ni]);
                MMA16816(d[mi][ni], a0f[mi], b1f[ni]);
                MMA16816(d[mi][ni], a1f[mi], b0f[ni]);
            }
        }
    }

    __syncthreads();   // s_qx ready; smem_t free to write

    // ---- epilogue in registers -> padded smem (exact validated fp ops) ----
    const float lam = g_lam, oml = g_one_m_lam, temp = g_temp;
#pragma unroll
    for (int mi = 0; mi < 4; mi++) {
#pragma unroll
        for (int rh = 0; rh < 2; rh++) {
            int lr = wm + mi * 16 + gid + rh * 8;
            int m = m0 + lr;
            float px = pos[2 * m], py = pos[2 * m + 1];
            float sqa = __fadd_rn(__fmul_rn(px, px), __fmul_rn(py, py));
#pragma unroll
            for (int ni = 0; ni < 4; ni++) {
#pragma unroll
                for (int cc = 0; cc < 2; cc++) {
                    int lc = wn + ni * 8 + 2 * tig + cc;
                    float sim = d[mi][ni][rh * 2 + cc];
                    float qx = s_qx[lc], qy = s_qy[lc];
                    float P = __fmaf_rn(py, qy, __fmul_rn(px, qx));
                    float S = __fadd_rn(sqa, s_sqb[lc]);
                    float d2 = __fadd_rn(S, -(2.0f * P));
                    d2 = fmaxf(d2, 0.0f);
                    float sp = expf(-__fdiv_rn(d2, 5000.0f));
                    float comb = __fadd_rn(__fmul_rn(lam, sim),
                                           __fmul_rn(oml, sp));
                    smem_t[lr * 129 + lc] = sigmoid_f(__fmul_rn(comb, temp));
                }
            }
        }
    }
    __syncthreads();

    // ---- stores: normal rows + mirrored rows (conflict-free, stride 129) ----
    const bool diag = (bi == bj);
#pragma unroll 1
    for (int rr = 0; rr < 16; rr++) {
        int r = wid * 16 + rr;
        float* orow = outp + (size_t)(m0 + r) * NN + n0;
#pragma unroll
        for (int c = lane; c < 128; c += 32)
            orow[c] = smem_t[r * 129 + c];
        if (!diag) {
            float* mrow = outp + (size_t)(n0 + r) * NN + m0;
#pragma unroll
            for (int c2 = lane; c2 < 128; c2 += 32)
                mrow[c2] = smem_t[c2 * 129 + r];
        }
    }
}

// ---------------------------------------------------------------------------
// Kernel 3: per-row exact top-k IN PLACE + boundary-band refinement with
// reference-replica keys (validated round 6 — unchanged logic).
// ---------------------------------------------------------------------------
#define TAU 2e-5f
#define MAXBAND 128

__global__ void topk_kernel(float* __restrict__ out,
                            const int* __restrict__ kptr,
                            long long out_size) {
    const int row = blockIdx.x;
    const int tid = threadIdx.x;
    const int NT = 256;

    __shared__ int cnt[256];
    __shared__ unsigned int sh_pfx;
    __shared__ int sh_rem;
    __shared__ int sh_nabove, sh_bandcnt;
    __shared__ int bandidx[MAXBAND];
    __shared__ unsigned int bandkey[MAXBAND];
    __shared__ unsigned char bandkeep[MAXBAND];
    __shared__ double red_d[256];
    extern __shared__ unsigned int srow[];   // NN uint32

    const int k = *kptr;
    const unsigned int* arow =
        (const unsigned int*)(out + (size_t)row * NN);
    for (int j = tid; j < NN; j += NT) srow[j] = arow[j];
    if (tid == 0) { sh_pfx = 0u; sh_rem = k; sh_nabove = 0; sh_bandcnt = 0; }
    __syncthreads();

#pragma unroll 1
    for (int pass = 0; pass < 4; pass++) {
        int shift = 24 - 8 * pass;
        unsigned int hi_mask = (pass == 0) ? 0u : (0xFFFFFFFFu << (shift + 8));
        cnt[tid] = 0;
        __syncthreads();
        unsigned int pfx = sh_pfx;
        for (int j = tid; j < NN; j += NT) {
            unsigned int v = srow[j];
            if ((v & hi_mask) == pfx)
                atomicAdd(&cnt[(v >> shift) & 255], 1);
        }
        __syncthreads();
        if (tid == 0) {
            int rem = sh_rem;
            int b = 255;
            for (; b > 0; b--) {
                if (rem - cnt[b] <= 0) break;
                rem -= cnt[b];
            }
            sh_pfx = pfx | ((unsigned int)b << shift);
            sh_rem = rem;
        }
        __syncthreads();
    }

    const float Tf = __uint_as_float(sh_pfx);
    const float band_hi = Tf + TAU;
    const float band_lo = Tf - TAU;

    for (int j = tid; j < NN; j += NT) {
        float v = __uint_as_float(srow[j]);
        if (v > band_hi) {
            atomicAdd(&sh_nabove, 1);
        } else if (v >= band_lo) {
            int p = atomicAdd(&sh_bandcnt, 1);
            if (p < MAXBAND) bandidx[p] = j;
        }
    }
    __syncthreads();

    const int n_above = sh_nabove;
    const int band_cnt_raw = sh_bandcnt;
    const int band_cnt = min(band_cnt_raw, MAXBAND);
    const int need = k - n_above;     // >= 1 always

    bool refined = false;
    if (band_cnt_raw <= MAXBAND && band_cnt_raw > need) {
        refined = true;
        const float lamk = g_lam_key, omlk = g_oml_key, temp = g_temp;
        const float* fa = &g_featn[(size_t)row * DD];

        for (int c = 0; c < band_cnt; c++) {
            int j = bandidx[c];
            const float* fb = &g_featn[(size_t)j * DD];
            double part = 0.0;
            for (int t = tid; t < DD; t += NT)
                part += (double)fa[t] * (double)fb[t];
            red_d[tid] = part;
            __syncthreads();
            for (int s = 128; s > 0; s >>= 1) {
                if (tid < s) red_d[tid] += red_d[tid + s];
                __syncthreads();
            }
            if (tid == 0) {
                float simf = (float)red_d[0];   // correctly-rounded fp32 sim
                float a = ref_adj_key(simf, row, j, lamk, omlk, temp);
                bandkey[c] = __float_as_uint(a);
                bandkeep[c] = 0;
            }
            __syncthreads();
        }
        if (tid == 0) {
            for (int pick = 0; pick < need; pick++) {
                int best = -1;
                for (int c = 0; c < band_cnt; c++) {
                    if (bandkeep[c]) continue;
                    if (best < 0 ||
                        bandkey[c] > bandkey[best] ||
                        (bandkey[c] == bandkey[best] && bandidx[c] < bandidx[best]))
                        best = c;
                }
                bandkeep[best] = 1;
            }
        }
        __syncthreads();
    }

    float* orow = out + (size_t)row * NN;
    const unsigned int Tkey = sh_pfx;
    for (int j = tid; j < NN; j += NT) {
        unsigned int vb = srow[j];
        float v = __uint_as_float(vb);
        float o = 0.0f;
        if (v > band_hi) {
            o = v;
        } else if (v >= band_lo) {
            if (!refined) {
                if (band_cnt_raw <= MAXBAND) {
                    o = v;                       // band_cnt == need: keep all
                } else {
                    o = (vb >= Tkey) ? v : 0.0f; // overflow fallback
                }
            } else {
                for (int c = 0; c < band_cnt; c++) {
                    if (bandidx[c] == j) { o = bandkeep[c] ? v : 0.0f; break; }
                }
            }
        }
        orow[j] = o;
    }

    if (row == 0 && tid == 0 && out_size > (long long)NN * NN)
        out[(size_t)NN * NN] = g_lam;    // second tuple output: lam scalar
}

// ---------------------------------------------------------------------------
extern "C" void kernel_launch(void* const* d_in, const int* in_sizes, int n_in,
                              void* d_out, int out_size) {
    const float* feat = (const float*)d_in[0];   // (8192, 512)
    const float* pos  = (const float*)d_in[1];   // (8192, 2)
    const float* lamw = (const float*)d_in[2];   // scalar
    const float* temp = (const float*)d_in[3];   // scalar
    const int*   kptr = (const int*)d_in[4];     // scalar int
    float* out = (float*)d_out;

    cudaFuncSetAttribute(adj_gemm_mma,
                         cudaFuncAttributeMaxDynamicSharedMemorySize, EPI_SMEM);

    prep_kernel<<<NN / 8, 256>>>(feat, pos, lamw, temp);
    adj_gemm_mma<<<NPAIRS, 256, EPI_SMEM>>>(pos, out);
    topk_kernel<<<NN, 256, NN * sizeof(unsigned int)>>>(out, kptr,
                                                        (long long)out_size);
}

// round 11
// speedup vs baseline: 2.5863x; 1.5594x over previous
#include <cuda_runtime.h>
#include <cuda_bf16.h>
#include <math.h>

#define NN 8192
#define DD 512

// Scratch (static device globals — no runtime allocation allowed)
__device__ float g_featn[(size_t)NN * DD];                     // normalized feats
__device__ __align__(16) __nv_bfloat16 g_sp0[(size_t)NN * DD]; // bf16 split hi
__device__ __align__(16) __nv_bfloat16 g_sp1[(size_t)NN * DD]; // bf16 split lo
__device__ float g_pos[(size_t)NN * 2];
__device__ float g_lam, g_one_m_lam, g_temp;        // exp-form (output values)
__device__ float g_lam_key, g_oml_key;              // XLA tanh-form (ranking keys)

// m16n8k16 bf16 MMA, fp32 accumulate (plain PTX, valid on sm_103)
#define MMA16816(d, a, b0v, b1v)                                              \
    asm volatile(                                                             \
        "mma.sync.aligned.m16n8k16.row.col.f32.bf16.bf16.f32 "                \
        "{%0,%1,%2,%3}, {%4,%5,%6,%7}, {%8,%9}, {%0,%1,%2,%3};"               \
        : "+f"((d)[0]), "+f"((d)[1]), "+f"((d)[2]), "+f"((d)[3])              \
        : "r"((a)[0]), "r"((a)[1]), "r"((a)[2]), "r"((a)[3]),                 \
          "r"(b0v), "r"(b1v))

#define LDSM_X4(r, addr)                                                      \
    asm volatile("ldmatrix.sync.aligned.m8n8.x4.shared.b16 {%0,%1,%2,%3}, [%4];" \
        : "=r"((r)[0]), "=r"((r)[1]), "=r"((r)[2]), "=r"((r)[3]) : "r"(addr))

#define CP_ASYNC16(dst, src)                                                  \
    asm volatile("cp.async.ca.shared.global [%0], [%1], 16;" :: "r"(dst), "l"(src))
#define CP_COMMIT() asm volatile("cp.async.commit_group;" ::: "memory")
#define CP_WAIT1()  asm volatile("cp.async.wait_group 1;" ::: "memory")
#define CP_WAIT0()  asm volatile("cp.async.wait_group 0;" ::: "memory")

__device__ __forceinline__ unsigned int smem_u32(const void* p) {
    return (unsigned int)__cvta_generic_to_shared(p);
}

// ---------------------------------------------------------------------------
// Numerics helpers (validated rounds 1-6 — DO NOT CHANGE)
// ---------------------------------------------------------------------------
__device__ __forceinline__ float sigmoid_f(float x) {
    if (x >= 0.0f) {
        float e = expf(-x);
        return __fdiv_rn(1.0f, __fadd_rn(1.0f, e));
    } else {
        float e = expf(x);
        return __fdiv_rn(e, __fadd_rn(1.0f, e));
    }
}

__device__ __forceinline__ float xla_tanh_f32(float x) {
    const float kClamp = 7.90531110763549805f;
    float xc = fminf(fmaxf(x, -kClamp), kClamp);
    float x2 = __fmul_rn(xc, xc);
    float p = __fmaf_rn(x2, -2.76076847742355e-16f, 2.00018790482477e-13f);
    p = __fmaf_rn(x2, p, -8.60467152213735e-11f);
    p = __fmaf_rn(x2, p, 5.12229709037114e-08f);
    p = __fmaf_rn(x2, p, 1.48572235717979e-05f);
    p = __fmaf_rn(x2, p, 6.37261928875436e-04f);
    p = __fmaf_rn(x2, p, 4.89352455891786e-03f);
    float num = __fmul_rn(xc, p);
    float q = __fmaf_rn(x2, 1.19825839466702e-06f, 1.18534705686654e-04f);
    q = __fmaf_rn(x2, q, 2.26843463243900e-03f);
    q = __fmaf_rn(x2, q, 4.89352518554385e-03f);
    float r = __fdiv_rn(num, q);
    return (fabsf(x) < 0.0004f) ? x : r;
}

__device__ __forceinline__ float xla_logistic_f32(float x) {
    float t = xla_tanh_f32(__fmul_rn(0.5f, x));
    return __fadd_rn(0.5f, __fmul_rn(0.5f, t));
}

__device__ __forceinline__ float ref_adj_key(float simf, int i, int j,
                                             float lamk, float omlk, float temp) {
    float px = g_pos[2 * i], py = g_pos[2 * i + 1];
    float qx = g_pos[2 * j], qy = g_pos[2 * j + 1];
    float sqa = __fadd_rn(__fmul_rn(px, px), __fmul_rn(py, py));
    float sqb = __fadd_rn(__fmul_rn(qx, qx), __fmul_rn(qy, qy));
    float P = __fmaf_rn(py, qy, __fmul_rn(px, qx));
    float S = __fadd_rn(sqa, sqb);
    float d2 = __fadd_rn(S, -(2.0f * P));
    d2 = fmaxf(d2, 0.0f);
    float arg = -__fdiv_rn(d2, 5000.0f);
    float sp = (float)exp((double)arg);     // correctly-rounded fp32 exp
    float comb = __fadd_rn(__fmul_rn(lamk, simf), __fmul_rn(omlk, sp));
    float z = __fmul_rn(comb, temp);
    return xla_logistic_f32(z);
}

// ---------------------------------------------------------------------------
// Kernel 1: row-normalize (fp64 norm) + 2-way bf16 split of normalized feats.
// ---------------------------------------------------------------------------
__global__ void prep_kernel(const float* __restrict__ feat,
                            const float* __restrict__ pos,
                            const float* __restrict__ lamw,
                            const float* __restrict__ temp) {
    int gwarp = (blockIdx.x * blockDim.x + threadIdx.x) >> 5;
    int lane = threadIdx.x & 31;
    if (gwarp >= NN) return;
    const float* src = feat + (size_t)gwarp * DD;

    double ss = 0.0;
#pragma unroll
    for (int j = lane; j < DD; j += 32) {
        double v = (double)src[j];
        ss += v * v;
    }
#pragma unroll
    for (int off = 16; off > 0; off >>= 1)
        ss += __shfl_down_sync(0xFFFFFFFFu, ss, off);
    ss = __shfl_sync(0xFFFFFFFFu, ss, 0);

    float nrm = fmaxf((float)sqrt(ss), 1e-12f);
    size_t base = (size_t)gwarp * DD;
#pragma unroll
    for (int j = lane; j < DD; j += 32) {
        float v = __fdiv_rn(src[j], nrm);
        g_featn[base + j] = v;
        __nv_bfloat16 b0 = __float2bfloat16_rn(v);
        float r1 = v - __bfloat162float(b0);
        __nv_bfloat16 b1 = __float2bfloat16_rn(r1);
        g_sp0[base + j] = b0;
        g_sp1[base + j] = b1;
    }

    if (lane < 2) g_pos[2 * gwarp + lane] = pos[2 * gwarp + lane];
    if (gwarp == 0 && lane == 0) {
        float lam = sigmoid_f(*lamw);
        g_lam = lam;
        g_one_m_lam = 1.0f - lam;
        g_temp = *temp;
        float lamk = xla_logistic_f32(*lamw);   // reference's lam
        g_lam_key = lamk;
        g_oml_key = __fadd_rn(1.0f, -lamk);
    }
}

// ---------------------------------------------------------------------------
// Kernel 2: mma.sync bf16 2-split GEMM, smem-staged (cp.async double buffer)
// + ldmatrix fragment feed (B non-trans: b-fragment wants k-consecutive pairs
// at fixed n, which row-addressed non-trans ldmatrix delivers directly).
// Same MMA order as round 9 -> bitwise identical sim.
// ---------------------------------------------------------------------------
#define NTILE (NN / 128)                   // 64
#define NPAIRS (NTILE * (NTILE + 1) / 2)   // 2080
#define STAGE 65536                        // one buffer: 4 mats x 16 KB
#define DYN_SMEM (2 * STAGE)               // 128 KB (epilogue overlays)

// stage one 64-col k-chunk into buffer `base` (swizzled, coalesced)
__device__ __forceinline__ void stage_chunk(unsigned int base, int m0, int n0,
                                            int k0, int tid) {
#pragma unroll
    for (int it = 0; it < 16; it++) {
        int u = it * 256 + tid;        // 0..4095
        int mat = u >> 10;             // 0:A0 1:A1 2:B0 3:B1
        int idx = u & 1023;
        int row = idx >> 3;
        int grp = idx & 7;
        int grow = ((mat < 2) ? m0 : n0) + row;
        const __nv_bfloat16* g = (mat == 0 || mat == 2) ? g_sp0 : g_sp1;
        const void* src = (const void*)(g + (size_t)grow * DD + k0 + grp * 8);
        unsigned int dst = base + (unsigned)(mat * 16384 + row * 128 +
                                             ((grp ^ (row & 7)) << 4));
        CP_ASYNC16(dst, src);
    }
}

__global__ __launch_bounds__(256, 1)
void adj_gemm_mma(const float* __restrict__ pos, float* __restrict__ outp) {
    extern __shared__ char dyn[];
    __shared__ float s_qx[128], s_qy[128], s_sqb[128];

    // decode linear tile id -> (bi, bj), bj >= bi
    int t = blockIdx.x;
    int bi = (int)((2.0 * NTILE + 1.0 -
                    sqrt((2.0 * NTILE + 1.0) * (2.0 * NTILE + 1.0) - 8.0 * (double)t)) * 0.5);
    while ((bi + 1) * NTILE - ((bi + 1) * bi) / 2 <= t) bi++;
    while (bi * NTILE - (bi * (bi - 1)) / 2 > t) bi--;
    int bj = bi + (t - (bi * NTILE - (bi * (bi - 1)) / 2));

    const int m0 = bi * 128, n0 = bj * 128;
    const int tid = threadIdx.x;
    const int wid = tid >> 5;
    const int lane = tid & 31;
    const int gid = lane >> 2;
    const int tig = lane & 3;
    const int lane7 = lane & 7;

    const int wm = (wid >> 2) * 64;   // warp m-offset (0 or 64)
    const int wn = (wid & 3) * 32;    // warp n-offset (0..96)

    // ldmatrix per-lane row/group selectors
    const int ra  = wm + ((lane & 8) ? 8 : 0) + lane7;     // A row (per mi +16)
    const int gsa = (lane >> 4) & 1;                       // A kgroup select
    const int rb  = wn + ((lane & 16) ? 8 : 0) + lane7;    // B row (per pair +16)
    const int gsb = (lane >> 3) & 1;                       // B kgroup select

    const unsigned int sbase = smem_u32(dyn);

    if (tid < 128) {
        int n = n0 + tid;
        float qx = pos[2 * n], qy = pos[2 * n + 1];
        s_qx[tid] = qx; s_qy[tid] = qy;
        s_sqb[tid] = __fadd_rn(__fmul_rn(qx, qx), __fmul_rn(qy, qy));
    }

    float d[4][4][4];
#pragma unroll
    for (int mi = 0; mi < 4; mi++)
#pragma unroll
        for (int ni = 0; ni < 4; ni++)
#pragma unroll
            for (int r = 0; r < 4; r++) d[mi][ni][r] = 0.0f;

    stage_chunk(sbase, m0, n0, 0, tid);
    CP_COMMIT();

#pragma unroll 1
    for (int ch = 0; ch < 8; ch++) {
        if (ch < 7) {
            stage_chunk(sbase + ((ch + 1) & 1) * STAGE, m0, n0, (ch + 1) * 64, tid);
            CP_COMMIT();
            CP_WAIT1();
        } else {
            CP_WAIT0();
        }
        __syncthreads();

        const unsigned int buf = sbase + (ch & 1) * STAGE;
#pragma unroll
        for (int ks = 0; ks < 4; ks++) {
            const unsigned int swa = (unsigned)(((ks * 2 + gsa) ^ lane7) << 4);
            const unsigned int swb = (unsigned)(((ks * 2 + gsb) ^ lane7) << 4);
            unsigned int a[2][4][4], b[2][2][4];
#pragma unroll
            for (int s = 0; s < 2; s++)
#pragma unroll
                for (int mi = 0; mi < 4; mi++) {
                    unsigned int ad = buf + (unsigned)(s * 16384 +
                                        (ra + mi * 16) * 128) + swa;
                    LDSM_X4(a[s][mi], ad);
                }
#pragma unroll
            for (int s = 0; s < 2; s++)
#pragma unroll
                for (int p = 0; p < 2; p++) {
                    unsigned int bd = buf + (unsigned)((2 + s) * 16384 +
                                        (rb + p * 16) * 128) + swb;
                    LDSM_X4(b[s][p], bd);
                }
#pragma unroll
            for (int mi = 0; mi < 4; mi++) {
#pragma unroll
                for (int ni = 0; ni < 4; ni++) {
                    const int p = ni >> 1, o = (ni & 1) * 2;
                    MMA16816(d[mi][ni], a[0][mi], b[0][p][o], b[0][p][o + 1]);
                    MMA16816(d[mi][ni], a[0][mi], b[1][p][o], b[1][p][o + 1]);
                    MMA16816(d[mi][ni], a[1][mi], b[0][p][o], b[0][p][o + 1]);
                }
            }
        }
        __syncthreads();   // all warps done reading buf before re-stage
    }

    // ---- epilogue in registers -> padded smem (exact validated fp ops) ----
    float* smem_t = (float*)dyn;   // 128 x 129 floats (staging done)
    const float lam = g_lam, oml = g_one_m_lam, temp = g_temp;
#pragma unroll
    for (int mi = 0; mi < 4; mi++) {
#pragma unroll
        for (int rh = 0; rh < 2; rh++) {
            int lr = wm + mi * 16 + gid + rh * 8;
            int m = m0 + lr;
            float px = pos[2 * m], py = pos[2 * m + 1];
            float sqa = __fadd_rn(__fmul_rn(px, px), __fmul_rn(py, py));
#pragma unroll
            for (int ni = 0; ni < 4; ni++) {
#pragma unroll
                for (int cc = 0; cc < 2; cc++) {
                    int lc = wn + ni * 8 + 2 * tig + cc;
                    float sim = d[mi][ni][rh * 2 + cc];
                    float qx = s_qx[lc], qy = s_qy[lc];
                    float P = __fmaf_rn(py, qy, __fmul_rn(px, qx));
                    float S = __fadd_rn(sqa, s_sqb[lc]);
                    float d2 = __fadd_rn(S, -(2.0f * P));
                    d2 = fmaxf(d2, 0.0f);
                    float sp = expf(-__fdiv_rn(d2, 5000.0f));
                    float comb = __fadd_rn(__fmul_rn(lam, sim),
                                           __fmul_rn(oml, sp));
                    smem_t[lr * 129 + lc] = sigmoid_f(__fmul_rn(comb, temp));
                }
            }
        }
    }
    __syncthreads();

    // ---- stores: normal rows + mirrored rows (conflict-free, stride 129) ----
    const bool diag = (bi == bj);
#pragma unroll 1
    for (int rr = 0; rr < 16; rr++) {
        int r = wid * 16 + rr;
        float* orow = outp + (size_t)(m0 + r) * NN + n0;
#pragma unroll
        for (int c = lane; c < 128; c += 32)
            orow[c] = smem_t[r * 129 + c];
        if (!diag) {
            float* mrow = outp + (size_t)(n0 + r) * NN + m0;
#pragma unroll
            for (int c2 = lane; c2 < 128; c2 += 32)
                mrow[c2] = smem_t[c2 * 129 + r];
        }
    }
}

// ---------------------------------------------------------------------------
// Kernel 3: per-row exact top-k IN PLACE + boundary-band refinement with
// reference-replica keys (validated round 6 — unchanged logic).
// ---------------------------------------------------------------------------
#define TAU 2e-5f
#define MAXBAND 128

__global__ void topk_kernel(float* __restrict__ out,
                            const int* __restrict__ kptr,
                            long long out_size) {
    const int row = blockIdx.x;
    const int tid = threadIdx.x;
    const int NT = 256;

    __shared__ int cnt[256];
    __shared__ unsigned int sh_pfx;
    __shared__ int sh_rem;
    __shared__ int sh_nabove, sh_bandcnt;
    __shared__ int bandidx[MAXBAND];
    __shared__ unsigned int bandkey[MAXBAND];
    __shared__ unsigned char bandkeep[MAXBAND];
    __shared__ double red_d[256];
    extern __shared__ unsigned int srow[];   // NN uint32

    const int k = *kptr;
    const unsigned int* arow =
        (const unsigned int*)(out + (size_t)row * NN);
    for (int j = tid; j < NN; j += NT) srow[j] = arow[j];
    if (tid == 0) { sh_pfx = 0u; sh_rem = k; sh_nabove = 0; sh_bandcnt = 0; }
    __syncthreads();

#pragma unroll 1
    for (int pass = 0; pass < 4; pass++) {
        int shift = 24 - 8 * pass;
        unsigned int hi_mask = (pass == 0) ? 0u : (0xFFFFFFFFu << (shift + 8));
        cnt[tid] = 0;
        __syncthreads();
        unsigned int pfx = sh_pfx;
        for (int j = tid; j < NN; j += NT) {
            unsigned int v = srow[j];
            if ((v & hi_mask) == pfx)
                atomicAdd(&cnt[(v >> shift) & 255], 1);
        }
        __syncthreads();
        if (tid == 0) {
            int rem = sh_rem;
            int b = 255;
            for (; b > 0; b--) {
                if (rem - cnt[b] <= 0) break;
                rem -= cnt[b];
            }
            sh_pfx = pfx | ((unsigned int)b << shift);
            sh_rem = rem;
        }
        __syncthreads();
    }

    const float Tf = __uint_as_float(sh_pfx);
    const float band_hi = Tf + TAU;
    const float band_lo = Tf - TAU;

    for (int j = tid; j < NN; j += NT) {
        float v = __uint_as_float(srow[j]);
        if (v > band_hi) {
            atomicAdd(&sh_nabove, 1);
        } else if (v >= band_lo) {
            int p = atomicAdd(&sh_bandcnt, 1);
            if (p < MAXBAND) bandidx[p] = j;
        }
    }
    __syncthreads();

    const int n_above = sh_nabove;
    const int band_cnt_raw = sh_bandcnt;
    const int band_cnt = min(band_cnt_raw, MAXBAND);
    const int need = k - n_above;     // >= 1 always

    bool refined = false;
    if (band_cnt_raw <= MAXBAND && band_cnt_raw > need) {
        refined = true;
        const float lamk = g_lam_key, omlk = g_oml_key, temp = g_temp;
        const float* fa = &g_featn[(size_t)row * DD];

        for (int c = 0; c < band_cnt; c++) {
            int j = bandidx[c];
            const float* fb = &g_featn[(size_t)j * DD];
            double part = 0.0;
            for (int t = tid; t < DD; t += NT)
                part += (double)fa[t] * (double)fb[t];
            red_d[tid] = part;
            __syncthreads();
            for (int s = 128; s > 0; s >>= 1) {
                if (tid < s) red_d[tid] += red_d[tid + s];
                __syncthreads();
            }
            if (tid == 0) {
                float simf = (float)red_d[0];   // correctly-rounded fp32 sim
                float a = ref_adj_key(simf, row, j, lamk, omlk, temp);
                bandkey[c] = __float_as_uint(a);
                bandkeep[c] = 0;
            }
            __syncthreads();
        }
        if (tid == 0) {
            for (int pick = 0; pick < need; pick++) {
                int best = -1;
                for (int c = 0; c < band_cnt; c++) {
                    if (bandkeep[c]) continue;
                    if (best < 0 ||
                        bandkey[c] > bandkey[best] ||
                        (bandkey[c] == bandkey[best] && bandidx[c] < bandidx[best]))
                        best = c;
                }
                bandkeep[best] = 1;
            }
        }
        __syncthreads();
    }

    float* orow = out + (size_t)row * NN;
    const unsigned int Tkey = sh_pfx;
    for (int j = tid; j < NN; j += NT) {
        unsigned int vb = srow[j];
        float v = __uint_as_float(vb);
        float o = 0.0f;
        if (v > band_hi) {
            o = v;
        } else if (v >= band_lo) {
            if (!refined) {
                if (band_cnt_raw <= MAXBAND) {
                    o = v;                       // band_cnt == need: keep all
                } else {
                    o = (vb >= Tkey) ? v : 0.0f; // overflow fallback
                }
            } else {
                for (int c = 0; c < band_cnt; c++) {
                    if (bandidx[c] == j) { o = bandkeep[c] ? v : 0.0f; break; }
                }
            }
        }
        orow[j] = o;
    }

    if (row == 0 && tid == 0 && out_size > (long long)NN * NN)
        out[(size_t)NN * NN] = g_lam;    // second tuple output: lam scalar
}

// ---------------------------------------------------------------------------
extern "C" void kernel_launch(void* const* d_in, const int* in_sizes, int n_in,
                              void* d_out, int out_size) {
    const float* feat = (const float*)d_in[0];   // (8192, 512)
    const float* pos  = (const float*)d_in[1];   // (8192, 2)
    const float* lamw = (const float*)d_in[2];   // scalar
    const float* temp = (const float*)d_in[3];   // scalar
    const int*   kptr = (const int*)d_in[4];     // scalar int
    float* out = (float*)d_out;

    cudaFuncSetAttribute(adj_gemm_mma,
                         cudaFuncAttributeMaxDynamicSharedMemorySize, DYN_SMEM);

    prep_kernel<<<NN / 8, 256>>>(feat, pos, lamw, temp);
    adj_gemm_mma<<<NPAIRS, 256, DYN_SMEM>>>(pos, out);
    topk_kernel<<<NN, 256, NN * sizeof(unsigned int)>>>(out, kptr,
                                                        (long long)out_size);
}

// round 12
// speedup vs baseline: 2.6805x; 1.0364x over previous
#include <cuda_runtime.h>
#include <cuda_bf16.h>
#include <math.h>

#define NN 8192
#define DD 512

// Scratch (static device globals — no runtime allocation allowed)
__device__ float g_featn[(size_t)NN * DD];                     // normalized feats
__device__ __align__(16) __nv_bfloat16 g_sp0[(size_t)NN * DD]; // bf16 split hi
__device__ __align__(16) __nv_bfloat16 g_sp1[(size_t)NN * DD]; // bf16 split lo
__device__ float g_pos[(size_t)NN * 2];
__device__ float g_lam, g_one_m_lam, g_temp;        // exp-form (output values)
__device__ float g_lam_key, g_oml_key;              // XLA tanh-form (ranking keys)

// m16n8k16 bf16 MMA, fp32 accumulate (plain PTX, valid on sm_103)
#define MMA16816(d, a, b0v, b1v)                                              \
    asm volatile(                                                             \
        "mma.sync.aligned.m16n8k16.row.col.f32.bf16.bf16.f32 "                \
        "{%0,%1,%2,%3}, {%4,%5,%6,%7}, {%8,%9}, {%0,%1,%2,%3};"               \
        : "+f"((d)[0]), "+f"((d)[1]), "+f"((d)[2]), "+f"((d)[3])              \
        : "r"((a)[0]), "r"((a)[1]), "r"((a)[2]), "r"((a)[3]),                 \
          "r"(b0v), "r"(b1v))

#define LDSM_X4(r, addr)                                                      \
    asm volatile("ldmatrix.sync.aligned.m8n8.x4.shared.b16 {%0,%1,%2,%3}, [%4];" \
        : "=r"((r)[0]), "=r"((r)[1]), "=r"((r)[2]), "=r"((r)[3]) : "r"(addr))

#define CP_ASYNC16(dst, src)                                                  \
    asm volatile("cp.async.ca.shared.global [%0], [%1], 16;" :: "r"(dst), "l"(src))
#define CP_COMMIT() asm volatile("cp.async.commit_group;" ::: "memory")
#define CP_WAIT0()  asm volatile("cp.async.wait_group 0;" ::: "memory")

__device__ __forceinline__ unsigned int smem_u32(const void* p) {
    return (unsigned int)__cvta_generic_to_shared(p);
}

// ---------------------------------------------------------------------------
// Numerics helpers (validated rounds 1-6 — DO NOT CHANGE)
// ---------------------------------------------------------------------------
__device__ __forceinline__ float sigmoid_f(float x) {
    if (x >= 0.0f) {
        float e = expf(-x);
        return __fdiv_rn(1.0f, __fadd_rn(1.0f, e));
    } else {
        float e = expf(x);
        return __fdiv_rn(e, __fadd_rn(1.0f, e));
    }
}

__device__ __forceinline__ float xla_tanh_f32(float x) {
    const float kClamp = 7.90531110763549805f;
    float xc = fminf(fmaxf(x, -kClamp), kClamp);
    float x2 = __fmul_rn(xc, xc);
    float p = __fmaf_rn(x2, -2.76076847742355e-16f, 2.00018790482477e-13f);
    p = __fmaf_rn(x2, p, -8.60467152213735e-11f);
    p = __fmaf_rn(x2, p, 5.12229709037114e-08f);
    p = __fmaf_rn(x2, p, 1.48572235717979e-05f);
    p = __fmaf_rn(x2, p, 6.37261928875436e-04f);
    p = __fmaf_rn(x2, p, 4.89352455891786e-03f);
    float num = __fmul_rn(xc, p);
    float q = __fmaf_rn(x2, 1.19825839466702e-06f, 1.18534705686654e-04f);
    q = __fmaf_rn(x2, q, 2.26843463243900e-03f);
    q = __fmaf_rn(x2, q, 4.89352518554385e-03f);
    float r = __fdiv_rn(num, q);
    return (fabsf(x) < 0.0004f) ? x : r;
}

__device__ __forceinline__ float xla_logistic_f32(float x) {
    float t = xla_tanh_f32(__fmul_rn(0.5f, x));
    return __fadd_rn(0.5f, __fmul_rn(0.5f, t));
}

__device__ __forceinline__ float ref_adj_key(float simf, int i, int j,
                                             float lamk, float omlk, float temp) {
    float px = g_pos[2 * i], py = g_pos[2 * i + 1];
    float qx = g_pos[2 * j], qy = g_pos[2 * j + 1];
    float sqa = __fadd_rn(__fmul_rn(px, px), __fmul_rn(py, py));
    float sqb = __fadd_rn(__fmul_rn(qx, qx), __fmul_rn(qy, qy));
    float P = __fmaf_rn(py, qy, __fmul_rn(px, qx));
    float S = __fadd_rn(sqa, sqb);
    float d2 = __fadd_rn(S, -(2.0f * P));
    d2 = fmaxf(d2, 0.0f);
    float arg = -__fdiv_rn(d2, 5000.0f);
    float sp = (float)exp((double)arg);     // correctly-rounded fp32 exp
    float comb = __fadd_rn(__fmul_rn(lamk, simf), __fmul_rn(omlk, sp));
    float z = __fmul_rn(comb, temp);
    return xla_logistic_f32(z);
}

// ---------------------------------------------------------------------------
// Kernel 1: row-normalize (fp64 norm) + 2-way bf16 split of normalized feats.
// ---------------------------------------------------------------------------
__global__ void prep_kernel(const float* __restrict__ feat,
                            const float* __restrict__ pos,
                            const float* __restrict__ lamw,
                            const float* __restrict__ temp) {
    int gwarp = (blockIdx.x * blockDim.x + threadIdx.x) >> 5;
    int lane = threadIdx.x & 31;
    if (gwarp >= NN) return;
    const float* src = feat + (size_t)gwarp * DD;

    double ss = 0.0;
#pragma unroll
    for (int j = lane; j < DD; j += 32) {
        double v = (double)src[j];
        ss += v * v;
    }
#pragma unroll
    for (int off = 16; off > 0; off >>= 1)
        ss += __shfl_down_sync(0xFFFFFFFFu, ss, off);
    ss = __shfl_sync(0xFFFFFFFFu, ss, 0);

    float nrm = fmaxf((float)sqrt(ss), 1e-12f);
    size_t base = (size_t)gwarp * DD;
#pragma unroll
    for (int j = lane; j < DD; j += 32) {
        float v = __fdiv_rn(src[j], nrm);
        g_featn[base + j] = v;
        __nv_bfloat16 b0 = __float2bfloat16_rn(v);
        float r1 = v - __bfloat162float(b0);
        __nv_bfloat16 b1 = __float2bfloat16_rn(r1);
        g_sp0[base + j] = b0;
        g_sp1[base + j] = b1;
    }

    if (lane < 2) g_pos[2 * gwarp + lane] = pos[2 * gwarp + lane];
    if (gwarp == 0 && lane == 0) {
        float lam = sigmoid_f(*lamw);
        g_lam = lam;
        g_one_m_lam = 1.0f - lam;
        g_temp = *temp;
        float lamk = xla_logistic_f32(*lamw);   // reference's lam
        g_lam_key = lamk;
        g_oml_key = __fadd_rn(1.0f, -lamk);
    }
}

// ---------------------------------------------------------------------------
// Kernel 2: mma.sync bf16 2-split GEMM, smem-staged cp.async double buffer,
// ldmatrix feed (B non-trans), single __syncthreads per chunk, MMA issued
// product-outer (independent accumulator chains; per-accumulator product
// order P0,P1,P2 preserved -> bitwise identical to round 11).
// ---------------------------------------------------------------------------
#define NTILE (NN / 128)                   // 64
#define NPAIRS (NTILE * (NTILE + 1) / 2)   // 2080
#define STAGE 65536                        // one buffer: 4 mats x 16 KB
#define DYN_SMEM (2 * STAGE)               // 128 KB (epilogue overlays)

// stage one 64-col k-chunk into buffer `base` (swizzled, coalesced)
__device__ __forceinline__ void stage_chunk(unsigned int base, int m0, int n0,
                                            int k0, int tid) {
#pragma unroll
    for (int it = 0; it < 16; it++) {
        int u = it * 256 + tid;        // 0..4095
        int mat = u >> 10;             // 0:A0 1:A1 2:B0 3:B1
        int idx = u & 1023;
        int row = idx >> 3;
        int grp = idx & 7;
        int grow = ((mat < 2) ? m0 : n0) + row;
        const __nv_bfloat16* g = (mat == 0 || mat == 2) ? g_sp0 : g_sp1;
        const void* src = (const void*)(g + (size_t)grow * DD + k0 + grp * 8);
        unsigned int dst = base + (unsigned)(mat * 16384 + row * 128 +
                                             ((grp ^ (row & 7)) << 4));
        CP_ASYNC16(dst, src);
    }
}

__global__ __launch_bounds__(256, 1)
void adj_gemm_mma(const float* __restrict__ pos, float* __restrict__ outp) {
    extern __shared__ char dyn[];
    __shared__ float s_qx[128], s_qy[128], s_sqb[128];

    // decode linear tile id -> (bi, bj), bj >= bi
    int t = blockIdx.x;
    int bi = (int)((2.0 * NTILE + 1.0 -
                    sqrt((2.0 * NTILE + 1.0) * (2.0 * NTILE + 1.0) - 8.0 * (double)t)) * 0.5);
    while ((bi + 1) * NTILE - ((bi + 1) * bi) / 2 <= t) bi++;
    while (bi * NTILE - (bi * (bi - 1)) / 2 > t) bi--;
    int bj = bi + (t - (bi * NTILE - (bi * (bi - 1)) / 2));

    const int m0 = bi * 128, n0 = bj * 128;
    const int tid = threadIdx.x;
    const int wid = tid >> 5;
    const int lane = tid & 31;
    const int gid = lane >> 2;
    const int tig = lane & 3;
    const int lane7 = lane & 7;

    const int wm = (wid >> 2) * 64;   // warp m-offset (0 or 64)
    const int wn = (wid & 3) * 32;    // warp n-offset (0..96)

    // ldmatrix per-lane row/group selectors
    const int ra  = wm + ((lane & 8) ? 8 : 0) + lane7;     // A row (per mi +16)
    const int gsa = (lane >> 4) & 1;                       // A kgroup select
    const int rb  = wn + ((lane & 16) ? 8 : 0) + lane7;    // B row (per pair +16)
    const int gsb = (lane >> 3) & 1;                       // B kgroup select

    const unsigned int sbase = smem_u32(dyn);

    if (tid < 128) {
        int n = n0 + tid;
        float qx = pos[2 * n], qy = pos[2 * n + 1];
        s_qx[tid] = qx; s_qy[tid] = qy;
        s_sqb[tid] = __fadd_rn(__fmul_rn(qx, qx), __fmul_rn(qy, qy));
    }

    float d[4][4][4];
#pragma unroll
    for (int mi = 0; mi < 4; mi++)
#pragma unroll
        for (int ni = 0; ni < 4; ni++)
#pragma unroll
            for (int r = 0; r < 4; r++) d[mi][ni][r] = 0.0f;

    stage_chunk(sbase, m0, n0, 0, tid);
    CP_COMMIT();

#pragma unroll 1
    for (int ch = 0; ch < 8; ch++) {
        CP_WAIT0();            // current chunk's data landed (this thread)
        __syncthreads();       // all threads landed + prev buffer drained
        if (ch < 7) {          // overlap next stage with current compute
            stage_chunk(sbase + ((ch + 1) & 1) * STAGE, m0, n0, (ch + 1) * 64, tid);
            CP_COMMIT();
        }

        const unsigned int buf = sbase + (ch & 1) * STAGE;
#pragma unroll
        for (int ks = 0; ks < 4; ks++) {
            const unsigned int swa = (unsigned)(((ks * 2 + gsa) ^ lane7) << 4);
            const unsigned int swb = (unsigned)(((ks * 2 + gsb) ^ lane7) << 4);
            unsigned int a[2][4][4], b[2][2][4];
#pragma unroll
            for (int s = 0; s < 2; s++)
#pragma unroll
                for (int mi = 0; mi < 4; mi++) {
                    unsigned int ad = buf + (unsigned)(s * 16384 +
                                        (ra + mi * 16) * 128) + swa;
                    LDSM_X4(a[s][mi], ad);
                }
#pragma unroll
            for (int s = 0; s < 2; s++)
#pragma unroll
                for (int p = 0; p < 2; p++) {
                    unsigned int bd = buf + (unsigned)((2 + s) * 16384 +
                                        (rb + p * 16) * 128) + swb;
                    LDSM_X4(b[s][p], bd);
                }
            // product-outer: 16 independent accumulators between reuses;
            // per-accumulator order P0,P1,P2 preserved (bitwise identical)
#pragma unroll
            for (int mi = 0; mi < 4; mi++)
#pragma unroll
                for (int ni = 0; ni < 4; ni++) {
                    const int p = ni >> 1, o = (ni & 1) * 2;
                    MMA16816(d[mi][ni], a[0][mi], b[0][p][o], b[0][p][o + 1]);
                }
#pragma unroll
            for (int mi = 0; mi < 4; mi++)
#pragma unroll
                for (int ni = 0; ni < 4; ni++) {
                    const int p = ni >> 1, o = (ni & 1) * 2;
                    MMA16816(d[mi][ni], a[0][mi], b[1][p][o], b[1][p][o + 1]);
                }
#pragma unroll
            for (int mi = 0; mi < 4; mi++)
#pragma unroll
                for (int ni = 0; ni < 4; ni++) {
                    const int p = ni >> 1, o = (ni & 1) * 2;
                    MMA16816(d[mi][ni], a[1][mi], b[0][p][o], b[0][p][o + 1]);
                }
        }
    }
    __syncthreads();   // all warps done with LDSM before smem_t overlay

    // ---- epilogue in registers -> padded smem (exact validated fp ops) ----
    float* smem_t = (float*)dyn;   // 128 x 129 floats (staging done)
    const float lam = g_lam, oml = g_one_m_lam, temp = g_temp;
#pragma unroll
    for (int mi = 0; mi < 4; mi++) {
#pragma unroll
        for (int rh = 0; rh < 2; rh++) {
            int lr = wm + mi * 16 + gid + rh * 8;
            int m = m0 + lr;
            float px = pos[2 * m], py = pos[2 * m + 1];
            float sqa = __fadd_rn(__fmul_rn(px, px), __fmul_rn(py, py));
#pragma unroll
            for (int ni = 0; ni < 4; ni++) {
#pragma unroll
                for (int cc = 0; cc < 2; cc++) {
                    int lc = wn + ni * 8 + 2 * tig + cc;
                    float sim = d[mi][ni][rh * 2 + cc];
                    float qx = s_qx[lc], qy = s_qy[lc];
                    float P = __fmaf_rn(py, qy, __fmul_rn(px, qx));
                    float S = __fadd_rn(sqa, s_sqb[lc]);
                    float d2 = __fadd_rn(S, -(2.0f * P));
                    d2 = fmaxf(d2, 0.0f);
                    float sp = expf(-__fdiv_rn(d2, 5000.0f));
                    float comb = __fadd_rn(__fmul_rn(lam, sim),
                                           __fmul_rn(oml, sp));
                    smem_t[lr * 129 + lc] = sigmoid_f(__fmul_rn(comb, temp));
                }
            }
        }
    }
    __syncthreads();

    // ---- stores: normal rows + mirrored rows (conflict-free, stride 129) ----
    const bool diag = (bi == bj);
#pragma unroll 1
    for (int rr = 0; rr < 16; rr++) {
        int r = wid * 16 + rr;
        float* orow = outp + (size_t)(m0 + r) * NN + n0;
#pragma unroll
        for (int c = lane; c < 128; c += 32)
            orow[c] = smem_t[r * 129 + c];
        if (!diag) {
            float* mrow = outp + (size_t)(n0 + r) * NN + m0;
#pragma unroll
            for (int c2 = lane; c2 < 128; c2 += 32)
                mrow[c2] = smem_t[c2 * 129 + r];
        }
    }
}

// ---------------------------------------------------------------------------
// Kernel 3: per-row exact top-k IN PLACE + boundary-band refinement with
// reference-replica keys. Histogram uses warp-aggregated atomics (values
// cluster near 0.5 -> few hot bins); bucket select is two-level (warp sums).
// Selection semantics identical to the validated serial version.
// ---------------------------------------------------------------------------
#define TAU 2e-5f
#define MAXBAND 128

__global__ void topk_kernel(float* __restrict__ out,
                            const int* __restrict__ kptr,
                            long long out_size) {
    const int row = blockIdx.x;
    const int tid = threadIdx.x;
    const int NT = 256;
    const int lane = tid & 31;

    __shared__ int cnt[256];
    __shared__ int wsum[8];
    __shared__ unsigned int sh_pfx;
    __shared__ int sh_rem;
    __shared__ int sh_nabove, sh_bandcnt;
    __shared__ int bandidx[MAXBAND];
    __shared__ unsigned int bandkey[MAXBAND];
    __shared__ unsigned char bandkeep[MAXBAND];
    __shared__ double red_d[256];
    extern __shared__ unsigned int srow[];   // NN uint32

    const int k = *kptr;
    const unsigned int* arow =
        (const unsigned int*)(out + (size_t)row * NN);
    for (int j = tid; j < NN; j += NT) srow[j] = arow[j];
    if (tid == 0) { sh_pfx = 0u; sh_rem = k; sh_nabove = 0; sh_bandcnt = 0; }
    __syncthreads();

#pragma unroll 1
    for (int pass = 0; pass < 4; pass++) {
        int shift = 24 - 8 * pass;
        unsigned int hi_mask = (pass == 0) ? 0u : (0xFFFFFFFFu << (shift + 8));
        cnt[tid] = 0;
        __syncthreads();
        unsigned int pfx = sh_pfx;
        for (int j = tid; j < NN; j += NT) {
            unsigned int v = srow[j];
            bool act = ((v & hi_mask) == pfx);
            unsigned int bin = (v >> shift) & 255;
            unsigned int bal = __ballot_sync(0xFFFFFFFFu, act);
            if (act) {
                unsigned int peers = __match_any_sync(bal, bin);
                int leader = __ffs(peers) - 1;
                if (lane == leader)
                    atomicAdd(&cnt[bin], __popc(peers));
            }
        }
        __syncthreads();
        // two-level select (bitwise-equivalent to serial 255->0 walk)
        {
            int wv = cnt[tid];
#pragma unroll
            for (int off = 16; off > 0; off >>= 1)
                wv += __shfl_down_sync(0xFFFFFFFFu, wv, off);
            if (lane == 0) wsum[tid >> 5] = wv;
        }
        __syncthreads();
        if (tid == 0) {
            int rem = sh_rem;
            int w = 7;
            for (; w > 0; w--) {
                if (rem - wsum[w] <= 0) break;
                rem -= wsum[w];
            }
            int b = w * 32 + 31;
            for (; b > w * 32; b--) {
                if (rem - cnt[b] <= 0) break;
                rem -= cnt[b];
            }
            sh_pfx = pfx | ((unsigned int)b << shift);
            sh_rem = rem;
        }
        __syncthreads();
    }

    const float Tf = __uint_as_float(sh_pfx);
    const float band_hi = Tf + TAU;
    const float band_lo = Tf - TAU;

    for (int j = tid; j < NN; j += NT) {
        float v = __uint_as_float(srow[j]);
        if (v > band_hi) {
            atomicAdd(&sh_nabove, 1);
        } else if (v >= band_lo) {
            int p = atomicAdd(&sh_bandcnt, 1);
            if (p < MAXBAND) bandidx[p] = j;
        }
    }
    __syncthreads();

    const int n_above = sh_nabove;
    const int band_cnt_raw = sh_bandcnt;
    const int band_cnt = min(band_cnt_raw, MAXBAND);
    const int need = k - n_above;     // >= 1 always

    bool refined = false;
    if (band_cnt_raw <= MAXBAND && band_cnt_raw > need) {
        refined = true;
        const float lamk = g_lam_key, omlk = g_oml_key, temp = g_temp;
        const float* fa = &g_featn[(size_t)row * DD];

        for (int c = 0; c < band_cnt; c++) {
            int j = bandidx[c];
            const float* fb = &g_featn[(size_t)j * DD];
            double part = 0.0;
            for (int t = tid; t < DD; t += NT)
                part += (double)fa[t] * (double)fb[t];
            red_d[tid] = part;
            __syncthreads();
            for (int s = 128; s > 0; s >>= 1) {
                if (tid < s) red_d[tid] += red_d[tid + s];
                __syncthreads();
            }
            if (tid == 0) {
                float simf = (float)red_d[0];   // correctly-rounded fp32 sim
                float a = ref_adj_key(simf, row, j, lamk, omlk, temp);
                bandkey[c] = __float_as_uint(a);
                bandkeep[c] = 0;
            }
            __syncthreads();
        }
        if (tid == 0) {
            for (int pick = 0; pick < need; pick++) {
                int best = -1;
                for (int c = 0; c < band_cnt; c++) {
                    if (bandkeep[c]) continue;
                    if (best < 0 ||
                        bandkey[c] > bandkey[best] ||
                        (bandkey[c] == bandkey[best] && bandidx[c] < bandidx[best]))
                        best = c;
                }
                bandkeep[best] = 1;
            }
        }
        __syncthreads();
    }

    float* orow = out + (size_t)row * NN;
    const unsigned int Tkey = sh_pfx;
    for (int j = tid; j < NN; j += NT) {
        unsigned int vb = srow[j];
        float v = __uint_as_float(vb);
        float o = 0.0f;
        if (v > band_hi) {
            o = v;
        } else if (v >= band_lo) {
            if (!refined) {
                if (band_cnt_raw <= MAXBAND) {
                    o = v;                       // band_cnt == need: keep all
                } else {
                    o = (vb >= Tkey) ? v : 0.0f; // overflow fallback
                }
            } else {
                for (int c = 0; c < band_cnt; c++) {
                    if (bandidx[c] == j) { o = bandkeep[c] ? v : 0.0f; break; }
                }
            }
        }
        orow[j] = o;
    }

    if (row == 0 && tid == 0 && out_size > (long long)NN * NN)
        out[(size_t)NN * NN] = g_lam;    // second tuple output: lam scalar
}

// ---------------------------------------------------------------------------
extern "C" void kernel_launch(void* const* d_in, const int* in_sizes, int n_in,
                              void* d_out, int out_size) {
    const float* feat = (const float*)d_in[0];   // (8192, 512)
    const float* pos  = (const float*)d_in[1];   // (8192, 2)
    const float* lamw = (const float*)d_in[2];   // scalar
    const float* temp = (const float*)d_in[3];   // scalar
    const int*   kptr = (const int*)d_in[4];     // scalar int
    float* out = (float*)d_out;

    cudaFuncSetAttribute(adj_gemm_mma,
                         cudaFuncAttributeMaxDynamicSharedMemorySize, DYN_SMEM);

    prep_kernel<<<NN / 8, 256>>>(feat, pos, lamw, temp);
    adj_gemm_mma<<<NPAIRS, 256, DYN_SMEM>>>(pos, out);
    topk_kernel<<<NN, 256, NN * sizeof(unsigned int)>>>(out, kptr,
                                                        (long long)out_size);
}

// round 13
// speedup vs baseline: 2.7422x; 1.0230x over previous
#include <cuda_runtime.h>
#include <cuda_bf16.h>
#include <math.h>

#define NN 8192
#define DD 512

// Scratch (static device globals — no runtime allocation allowed)
__device__ float g_featn[(size_t)NN * DD];                     // normalized feats
__device__ __align__(16) __nv_bfloat16 g_sp0[(size_t)NN * DD]; // bf16 split hi
__device__ __align__(16) __nv_bfloat16 g_sp1[(size_t)NN * DD]; // bf16 split lo
__device__ float g_pos[(size_t)NN * 2];
__device__ float g_lam, g_one_m_lam, g_temp;        // exp-form (output values)
__device__ float g_lam_key, g_oml_key;              // XLA tanh-form (ranking keys)

// m16n8k16 bf16 MMA, fp32 accumulate (plain PTX, valid on sm_103)
#define MMA16816(d, a, b0v, b1v)                                              \
    asm volatile(                                                             \
        "mma.sync.aligned.m16n8k16.row.col.f32.bf16.bf16.f32 "                \
        "{%0,%1,%2,%3}, {%4,%5,%6,%7}, {%8,%9}, {%0,%1,%2,%3};"               \
        : "+f"((d)[0]), "+f"((d)[1]), "+f"((d)[2]), "+f"((d)[3])              \
        : "r"((a)[0]), "r"((a)[1]), "r"((a)[2]), "r"((a)[3]),                 \
          "r"(b0v), "r"(b1v))

#define LDSM_X4(r, addr)                                                      \
    asm volatile("ldmatrix.sync.aligned.m8n8.x4.shared.b16 {%0,%1,%2,%3}, [%4];" \
        : "=r"((r)[0]), "=r"((r)[1]), "=r"((r)[2]), "=r"((r)[3]) : "r"(addr))

#define CP_ASYNC16(dst, src)                                                  \
    asm volatile("cp.async.ca.shared.global [%0], [%1], 16;" :: "r"(dst), "l"(src))
#define CP_COMMIT() asm volatile("cp.async.commit_group;" ::: "memory")
#define CP_WAIT0()  asm volatile("cp.async.wait_group 0;" ::: "memory")

__device__ __forceinline__ unsigned int smem_u32(const void* p) {
    return (unsigned int)__cvta_generic_to_shared(p);
}

// ---------------------------------------------------------------------------
// Numerics helpers (validated rounds 1-6 — DO NOT CHANGE)
// ---------------------------------------------------------------------------
__device__ __forceinline__ float sigmoid_f(float x) {
    if (x >= 0.0f) {
        float e = expf(-x);
        return __fdiv_rn(1.0f, __fadd_rn(1.0f, e));
    } else {
        float e = expf(x);
        return __fdiv_rn(e, __fadd_rn(1.0f, e));
    }
}

__device__ __forceinline__ float xla_tanh_f32(float x) {
    const float kClamp = 7.90531110763549805f;
    float xc = fminf(fmaxf(x, -kClamp), kClamp);
    float x2 = __fmul_rn(xc, xc);
    float p = __fmaf_rn(x2, -2.76076847742355e-16f, 2.00018790482477e-13f);
    p = __fmaf_rn(x2, p, -8.60467152213735e-11f);
    p = __fmaf_rn(x2, p, 5.12229709037114e-08f);
    p = __fmaf_rn(x2, p, 1.48572235717979e-05f);
    p = __fmaf_rn(x2, p, 6.37261928875436e-04f);
    p = __fmaf_rn(x2, p, 4.89352455891786e-03f);
    float num = __fmul_rn(xc, p);
    float q = __fmaf_rn(x2, 1.19825839466702e-06f, 1.18534705686654e-04f);
    q = __fmaf_rn(x2, q, 2.26843463243900e-03f);
    q = __fmaf_rn(x2, q, 4.89352518554385e-03f);
    float r = __fdiv_rn(num, q);
    return (fabsf(x) < 0.0004f) ? x : r;
}

__device__ __forceinline__ float xla_logistic_f32(float x) {
    float t = xla_tanh_f32(__fmul_rn(0.5f, x));
    return __fadd_rn(0.5f, __fmul_rn(0.5f, t));
}

__device__ __forceinline__ float ref_adj_key(float simf, int i, int j,
                                             float lamk, float omlk, float temp) {
    float px = g_pos[2 * i], py = g_pos[2 * i + 1];
    float qx = g_pos[2 * j], qy = g_pos[2 * j + 1];
    float sqa = __fadd_rn(__fmul_rn(px, px), __fmul_rn(py, py));
    float sqb = __fadd_rn(__fmul_rn(qx, qx), __fmul_rn(qy, qy));
    float P = __fmaf_rn(py, qy, __fmul_rn(px, qx));
    float S = __fadd_rn(sqa, sqb);
    float d2 = __fadd_rn(S, -(2.0f * P));
    d2 = fmaxf(d2, 0.0f);
    float arg = -__fdiv_rn(d2, 5000.0f);
    float sp = (float)exp((double)arg);     // correctly-rounded fp32 exp
    float comb = __fadd_rn(__fmul_rn(lamk, simf), __fmul_rn(omlk, sp));
    float z = __fmul_rn(comb, temp);
    return xla_logistic_f32(z);
}

// ---------------------------------------------------------------------------
// Kernel 1: row-normalize (fp64 norm) + 2-way bf16 split of normalized feats.
// ---------------------------------------------------------------------------
__global__ void prep_kernel(const float* __restrict__ feat,
                            const float* __restrict__ pos,
                            const float* __restrict__ lamw,
                            const float* __restrict__ temp) {
    int gwarp = (blockIdx.x * blockDim.x + threadIdx.x) >> 5;
    int lane = threadIdx.x & 31;
    if (gwarp >= NN) return;
    const float* src = feat + (size_t)gwarp * DD;

    double ss = 0.0;
#pragma unroll
    for (int j = lane; j < DD; j += 32) {
        double v = (double)src[j];
        ss += v * v;
    }
#pragma unroll
    for (int off = 16; off > 0; off >>= 1)
        ss += __shfl_down_sync(0xFFFFFFFFu, ss, off);
    ss = __shfl_sync(0xFFFFFFFFu, ss, 0);

    float nrm = fmaxf((float)sqrt(ss), 1e-12f);
    size_t base = (size_t)gwarp * DD;
#pragma unroll
    for (int j = lane; j < DD; j += 32) {
        float v = __fdiv_rn(src[j], nrm);
        g_featn[base + j] = v;
        __nv_bfloat16 b0 = __float2bfloat16_rn(v);
        float r1 = v - __bfloat162float(b0);
        __nv_bfloat16 b1 = __float2bfloat16_rn(r1);
        g_sp0[base + j] = b0;
        g_sp1[base + j] = b1;
    }

    if (lane < 2) g_pos[2 * gwarp + lane] = pos[2 * gwarp + lane];
    if (gwarp == 0 && lane == 0) {
        float lam = sigmoid_f(*lamw);
        g_lam = lam;
        g_one_m_lam = 1.0f - lam;
        g_temp = *temp;
        float lamk = xla_logistic_f32(*lamw);   // reference's lam
        g_lam_key = lamk;
        g_oml_key = __fadd_rn(1.0f, -lamk);
    }
}

// ---------------------------------------------------------------------------
// Kernel 2: mma.sync bf16 2-split GEMM, 512 threads (16 warps, 4x4 grid of
// 32x32 warp tiles -> 4 warps/SMSP for latency hiding). smem-staged cp.async
// double buffer, ldmatrix feed, product-outer MMA issue. Per-accumulator
// order (P0,P1,P2; ks asc; ch asc) preserved -> bitwise identical sim.
// ---------------------------------------------------------------------------
#define NTILE (NN / 128)                   // 64
#define NPAIRS (NTILE * (NTILE + 1) / 2)   // 2080
#define STAGE 65536                        // one buffer: 4 mats x 16 KB
#define DYN_SMEM (2 * STAGE)               // 128 KB (epilogue overlays)
#define GT 512                             // GEMM threads

// stage one 64-col k-chunk into buffer `base` (swizzled, coalesced)
__device__ __forceinline__ void stage_chunk(unsigned int base, int m0, int n0,
                                            int k0, int tid) {
#pragma unroll
    for (int it = 0; it < 8; it++) {
        int u = it * GT + tid;         // 0..4095
        int mat = u >> 10;             // 0:A0 1:A1 2:B0 3:B1
        int idx = u & 1023;
        int row = idx >> 3;
        int grp = idx & 7;
        int grow = ((mat < 2) ? m0 : n0) + row;
        const __nv_bfloat16* g = (mat == 0 || mat == 2) ? g_sp0 : g_sp1;
        const void* src = (const void*)(g + (size_t)grow * DD + k0 + grp * 8);
        unsigned int dst = base + (unsigned)(mat * 16384 + row * 128 +
                                             ((grp ^ (row & 7)) << 4));
        CP_ASYNC16(dst, src);
    }
}

__global__ __launch_bounds__(GT, 1)
void adj_gemm_mma(const float* __restrict__ pos, float* __restrict__ outp) {
    extern __shared__ char dyn[];
    __shared__ float s_qx[128], s_qy[128], s_sqb[128];

    // decode linear tile id -> (bi, bj), bj >= bi
    int t = blockIdx.x;
    int bi = (int)((2.0 * NTILE + 1.0 -
                    sqrt((2.0 * NTILE + 1.0) * (2.0 * NTILE + 1.0) - 8.0 * (double)t)) * 0.5);
    while ((bi + 1) * NTILE - ((bi + 1) * bi) / 2 <= t) bi++;
    while (bi * NTILE - (bi * (bi - 1)) / 2 > t) bi--;
    int bj = bi + (t - (bi * NTILE - (bi * (bi - 1)) / 2));

    const int m0 = bi * 128, n0 = bj * 128;
    const int tid = threadIdx.x;
    const int wid = tid >> 5;
    const int lane = tid & 31;
    const int gid = lane >> 2;
    const int tig = lane & 3;
    const int lane7 = lane & 7;

    const int wm = (wid >> 2) * 32;   // warp m-offset (0,32,64,96)
    const int wn = (wid & 3) * 32;    // warp n-offset (0,32,64,96)

    // ldmatrix per-lane row/group selectors
    const int ra  = wm + ((lane & 8) ? 8 : 0) + lane7;     // A row (per mi +16)
    const int gsa = (lane >> 4) & 1;                       // A kgroup select
    const int rb  = wn + ((lane & 16) ? 8 : 0) + lane7;    // B row (per pair +16)
    const int gsb = (lane >> 3) & 1;                       // B kgroup select

    const unsigned int sbase = smem_u32(dyn);

    if (tid < 128) {
        int n = n0 + tid;
        float qx = pos[2 * n], qy = pos[2 * n + 1];
        s_qx[tid] = qx; s_qy[tid] = qy;
        s_sqb[tid] = __fadd_rn(__fmul_rn(qx, qx), __fmul_rn(qy, qy));
    }

    float d[2][4][4];
#pragma unroll
    for (int mi = 0; mi < 2; mi++)
#pragma unroll
        for (int ni = 0; ni < 4; ni++)
#pragma unroll
            for (int r = 0; r < 4; r++) d[mi][ni][r] = 0.0f;

    stage_chunk(sbase, m0, n0, 0, tid);
    CP_COMMIT();

#pragma unroll 1
    for (int ch = 0; ch < 8; ch++) {
        CP_WAIT0();            // current chunk's data landed (this thread)
        __syncthreads();       // all threads landed + prev buffer drained
        if (ch < 7) {          // overlap next stage with current compute
            stage_chunk(sbase + ((ch + 1) & 1) * STAGE, m0, n0, (ch + 1) * 64, tid);
            CP_COMMIT();
        }

        const unsigned int buf = sbase + (ch & 1) * STAGE;
#pragma unroll
        for (int ks = 0; ks < 4; ks++) {
            const unsigned int swa = (unsigned)(((ks * 2 + gsa) ^ lane7) << 4);
            const unsigned int swb = (unsigned)(((ks * 2 + gsb) ^ lane7) << 4);
            unsigned int a[2][2][4], b[2][2][4];
#pragma unroll
            for (int s = 0; s < 2; s++)
#pragma unroll
                for (int mi = 0; mi < 2; mi++) {
                    unsigned int ad = buf + (unsigned)(s * 16384 +
                                        (ra + mi * 16) * 128) + swa;
                    LDSM_X4(a[s][mi], ad);
                }
#pragma unroll
            for (int s = 0; s < 2; s++)
#pragma unroll
                for (int p = 0; p < 2; p++) {
                    unsigned int bd = buf + (unsigned)((2 + s) * 16384 +
                                        (rb + p * 16) * 128) + swb;
                    LDSM_X4(b[s][p], bd);
                }
            // product-outer: 8 independent accumulators between reuses;
            // per-accumulator order P0,P1,P2 preserved (bitwise identical)
#pragma unroll
            for (int mi = 0; mi < 2; mi++)
#pragma unroll
                for (int ni = 0; ni < 4; ni++) {
                    const int p = ni >> 1, o = (ni & 1) * 2;
                    MMA16816(d[mi][ni], a[0][mi], b[0][p][o], b[0][p][o + 1]);
                }
#pragma unroll
            for (int mi = 0; mi < 2; mi++)
#pragma unroll
                for (int ni = 0; ni < 4; ni++) {
                    const int p = ni >> 1, o = (ni & 1) * 2;
                    MMA16816(d[mi][ni], a[0][mi], b[1][p][o], b[1][p][o + 1]);
                }
#pragma unroll
            for (int mi = 0; mi < 2; mi++)
#pragma unroll
                for (int ni = 0; ni < 4; ni++) {
                    const int p = ni >> 1, o = (ni & 1) * 2;
                    MMA16816(d[mi][ni], a[1][mi], b[0][p][o], b[0][p][o + 1]);
                }
        }
    }
    __syncthreads();   // all warps done with LDSM before smem_t overlay

    // ---- epilogue in registers -> padded smem (exact validated fp ops) ----
    float* smem_t = (float*)dyn;   // 128 x 129 floats (staging done)
    const float lam = g_lam, oml = g_one_m_lam, temp = g_temp;
#pragma unroll
    for (int mi = 0; mi < 2; mi++) {
#pragma unroll
        for (int rh = 0; rh < 2; rh++) {
            int lr = wm + mi * 16 + gid + rh * 8;
            int m = m0 + lr;
            float px = pos[2 * m], py = pos[2 * m + 1];
            float sqa = __fadd_rn(__fmul_rn(px, px), __fmul_rn(py, py));
#pragma unroll
            for (int ni = 0; ni < 4; ni++) {
#pragma unroll
                for (int cc = 0; cc < 2; cc++) {
                    int lc = wn + ni * 8 + 2 * tig + cc;
                    float sim = d[mi][ni][rh * 2 + cc];
                    float qx = s_qx[lc], qy = s_qy[lc];
                    float P = __fmaf_rn(py, qy, __fmul_rn(px, qx));
                    float S = __fadd_rn(sqa, s_sqb[lc]);
                    float d2 = __fadd_rn(S, -(2.0f * P));
                    d2 = fmaxf(d2, 0.0f);
                    float sp = expf(-__fdiv_rn(d2, 5000.0f));
                    float comb = __fadd_rn(__fmul_rn(lam, sim),
                                           __fmul_rn(oml, sp));
                    smem_t[lr * 129 + lc] = sigmoid_f(__fmul_rn(comb, temp));
                }
            }
        }
    }
    __syncthreads();

    // ---- stores: normal rows + mirrored rows (conflict-free, stride 129) ----
    const bool diag = (bi == bj);
#pragma unroll 1
    for (int rr = 0; rr < 8; rr++) {
        int r = wid * 8 + rr;
        float* orow = outp + (size_t)(m0 + r) * NN + n0;
#pragma unroll
        for (int c = lane; c < 128; c += 32)
            orow[c] = smem_t[r * 129 + c];
        if (!diag) {
            float* mrow = outp + (size_t)(n0 + r) * NN + m0;
#pragma unroll
            for (int c2 = lane; c2 < 128; c2 += 32)
                mrow[c2] = smem_t[c2 * 129 + r];
        }
    }
}

// ---------------------------------------------------------------------------
// Kernel 3: per-row exact top-k IN PLACE + boundary-band refinement with
// reference-replica keys — 512 threads (halved pass iterations). Selection
// and tie semantics identical to the validated version.
// ---------------------------------------------------------------------------
#define TAU 2e-5f
#define MAXBAND 128
#define KT 512

__global__ void topk_kernel(float* __restrict__ out,
                            const int* __restrict__ kptr,
                            long long out_size) {
    const int row = blockIdx.x;
    const int tid = threadIdx.x;
    const int NT = KT;
    const int lane = tid & 31;

    __shared__ int cnt[256];
    __shared__ int wsum[8];
    __shared__ unsigned int sh_pfx;
    __shared__ int sh_rem;
    __shared__ int sh_nabove, sh_bandcnt;
    __shared__ int bandidx[MAXBAND];
    __shared__ unsigned int bandkey[MAXBAND];
    __shared__ unsigned char bandkeep[MAXBAND];
    __shared__ double red_d[KT];
    extern __shared__ unsigned int srow[];   // NN uint32

    const int k = *kptr;
    const unsigned int* arow =
        (const unsigned int*)(out + (size_t)row * NN);
    for (int j = tid; j < NN; j += NT) srow[j] = arow[j];
    if (tid == 0) { sh_pfx = 0u; sh_rem = k; sh_nabove = 0; sh_bandcnt = 0; }
    __syncthreads();

#pragma unroll 1
    for (int pass = 0; pass < 4; pass++) {
        int shift = 24 - 8 * pass;
        unsigned int hi_mask = (pass == 0) ? 0u : (0xFFFFFFFFu << (shift + 8));
        if (tid < 256) cnt[tid] = 0;
        __syncthreads();
        unsigned int pfx = sh_pfx;
        for (int j = tid; j < NN; j += NT) {
            unsigned int v = srow[j];
            bool act = ((v & hi_mask) == pfx);
            unsigned int bin = (v >> shift) & 255;
            unsigned int bal = __ballot_sync(0xFFFFFFFFu, act);
            if (act) {
                unsigned int peers = __match_any_sync(bal, bin);
                int leader = __ffs(peers) - 1;
                if (lane == leader)
                    atomicAdd(&cnt[bin], __popc(peers));
            }
        }
        __syncthreads();
        // two-level select (bitwise-equivalent to serial 255->0 walk)
        if (tid < 256) {
            int wv = cnt[tid];
#pragma unroll
            for (int off = 16; off > 0; off >>= 1)
                wv += __shfl_down_sync(0xFFFFFFFFu, wv, off);
            if (lane == 0) wsum[tid >> 5] = wv;
        }
        __syncthreads();
        if (tid == 0) {
            int rem = sh_rem;
            int w = 7;
            for (; w > 0; w--) {
                if (rem - wsum[w] <= 0) break;
                rem -= wsum[w];
            }
            int b = w * 32 + 31;
            for (; b > w * 32; b--) {
                if (rem - cnt[b] <= 0) break;
                rem -= cnt[b];
            }
            sh_pfx = pfx | ((unsigned int)b << shift);
            sh_rem = rem;
        }
        __syncthreads();
    }

    const float Tf = __uint_as_float(sh_pfx);
    const float band_hi = Tf + TAU;
    const float band_lo = Tf - TAU;

    for (int j = tid; j < NN; j += NT) {
        float v = __uint_as_float(srow[j]);
        if (v > band_hi) {
            atomicAdd(&sh_nabove, 1);
        } else if (v >= band_lo) {
            int p = atomicAdd(&sh_bandcnt, 1);
            if (p < MAXBAND) bandidx[p] = j;
        }
    }
    __syncthreads();

    const int n_above = sh_nabove;
    const int band_cnt_raw = sh_bandcnt;
    const int band_cnt = min(band_cnt_raw, MAXBAND);
    const int need = k - n_above;     // >= 1 always

    bool refined = false;
    if (band_cnt_raw <= MAXBAND && band_cnt_raw > need) {
        refined = true;
        const float lamk = g_lam_key, omlk = g_oml_key, temp = g_temp;
        const float* fa = &g_featn[(size_t)row * DD];

        for (int c = 0; c < band_cnt; c++) {
            int j = bandidx[c];
            const float* fb = &g_featn[(size_t)j * DD];
            double part = 0.0;
            for (int t = tid; t < DD; t += NT)
                part += (double)fa[t] * (double)fb[t];
            red_d[tid] = part;
            __syncthreads();
            for (int s = KT / 2; s > 0; s >>= 1) {
                if (tid < s) red_d[tid] += red_d[tid + s];
                __syncthreads();
            }
            if (tid == 0) {
                float simf = (float)red_d[0];   // correctly-rounded fp32 sim
                float a = ref_adj_key(simf, row, j, lamk, omlk, temp);
                bandkey[c] = __float_as_uint(a);
                bandkeep[c] = 0;
            }
            __syncthreads();
        }
        if (tid == 0) {
            for (int pick = 0; pick < need; pick++) {
                int best = -1;
                for (int c = 0; c < band_cnt; c++) {
                    if (bandkeep[c]) continue;
                    if (best < 0 ||
                        bandkey[c] > bandkey[best] ||
                        (bandkey[c] == bandkey[best] && bandidx[c] < bandidx[best]))
                        best = c;
                }
                bandkeep[best] = 1;
            }
        }
        __syncthreads();
    }

    float* orow = out + (size_t)row * NN;
    const unsigned int Tkey = sh_pfx;
    for (int j = tid; j < NN; j += NT) {
        unsigned int vb = srow[j];
        float v = __uint_as_float(vb);
        float o = 0.0f;
        if (v > band_hi) {
            o = v;
        } else if (v >= band_lo) {
            if (!refined) {
                if (band_cnt_raw <= MAXBAND) {
                    o = v;                       // band_cnt == need: keep all
                } else {
                    o = (vb >= Tkey) ? v : 0.0f; // overflow fallback
                }
            } else {
                for (int c = 0; c < band_cnt; c++) {
                    if (bandidx[c] == j) { o = bandkeep[c] ? v : 0.0f; break; }
                }
            }
        }
        orow[j] = o;
    }

    if (row == 0 && tid == 0 && out_size > (long long)NN * NN)
        out[(size_t)NN * NN] = g_lam;    // second tuple output: lam scalar
}

// ---------------------------------------------------------------------------
extern "C" void kernel_launch(void* const* d_in, const int* in_sizes, int n_in,
                              void* d_out, int out_size) {
    const float* feat = (const float*)d_in[0];   // (8192, 512)
    const float* pos  = (const float*)d_in[1];   // (8192, 2)
    const float* lamw = (const float*)d_in[2];   // scalar
    const float* temp = (const float*)d_in[3];   // scalar
    const int*   kptr = (const int*)d_in[4];     // scalar int
    float* out = (float*)d_out;

    cudaFuncSetAttribute(adj_gemm_mma,
                         cudaFuncAttributeMaxDynamicSharedMemorySize, DYN_SMEM);

    prep_kernel<<<NN / 8, 256>>>(feat, pos, lamw, temp);
    adj_gemm_mma<<<NPAIRS, GT, DYN_SMEM>>>(pos, out);
    topk_kernel<<<NN, KT, NN * sizeof(unsigned int)>>>(out, kptr,
                                                       (long long)out_size);
}

// round 14
// speedup vs baseline: 3.0711x; 1.1199x over previous
#include <cuda_runtime.h>
#include <cuda_bf16.h>
#include <math.h>

#define NN 8192
#define DD 512

// Scratch (static device globals — no runtime allocation allowed)
__device__ float g_featn[(size_t)NN * DD];                     // normalized feats
__device__ __align__(16) __nv_bfloat16 g_sp0[(size_t)NN * DD]; // bf16 of featn
__device__ float g_pos[(size_t)NN * 2];
__device__ float g_lam, g_one_m_lam, g_temp;        // exp-form (output values)
__device__ float g_lam_key, g_oml_key;              // XLA tanh-form (ranking keys)

// m16n8k16 bf16 MMA, fp32 accumulate (plain PTX, valid on sm_103)
#define MMA16816(d, a, b0v, b1v)                                              \
    asm volatile(                                                             \
        "mma.sync.aligned.m16n8k16.row.col.f32.bf16.bf16.f32 "                \
        "{%0,%1,%2,%3}, {%4,%5,%6,%7}, {%8,%9}, {%0,%1,%2,%3};"               \
        : "+f"((d)[0]), "+f"((d)[1]), "+f"((d)[2]), "+f"((d)[3])              \
        : "r"((a)[0]), "r"((a)[1]), "r"((a)[2]), "r"((a)[3]),                 \
          "r"(b0v), "r"(b1v))

#define LDSM_X4(r, addr)                                                      \
    asm volatile("ldmatrix.sync.aligned.m8n8.x4.shared.b16 {%0,%1,%2,%3}, [%4];" \
        : "=r"((r)[0]), "=r"((r)[1]), "=r"((r)[2]), "=r"((r)[3]) : "r"(addr))

#define CP_ASYNC16(dst, src)                                                  \
    asm volatile("cp.async.ca.shared.global [%0], [%1], 16;" :: "r"(dst), "l"(src))
#define CP_COMMIT() asm volatile("cp.async.commit_group;" ::: "memory")
#define CP_WAIT0()  asm volatile("cp.async.wait_group 0;" ::: "memory")

__device__ __forceinline__ unsigned int smem_u32(const void* p) {
    return (unsigned int)__cvta_generic_to_shared(p);
}

// ---------------------------------------------------------------------------
// Numerics helpers (validated rounds 1-6 — DO NOT CHANGE)
// ---------------------------------------------------------------------------
__device__ __forceinline__ float sigmoid_f(float x) {
    if (x >= 0.0f) {
        float e = expf(-x);
        return __fdiv_rn(1.0f, __fadd_rn(1.0f, e));
    } else {
        float e = expf(x);
        return __fdiv_rn(e, __fadd_rn(1.0f, e));
    }
}

__device__ __forceinline__ float xla_tanh_f32(float x) {
    const float kClamp = 7.90531110763549805f;
    float xc = fminf(fmaxf(x, -kClamp), kClamp);
    float x2 = __fmul_rn(xc, xc);
    float p = __fmaf_rn(x2, -2.76076847742355e-16f, 2.00018790482477e-13f);
    p = __fmaf_rn(x2, p, -8.60467152213735e-11f);
    p = __fmaf_rn(x2, p, 5.12229709037114e-08f);
    p = __fmaf_rn(x2, p, 1.48572235717979e-05f);
    p = __fmaf_rn(x2, p, 6.37261928875436e-04f);
    p = __fmaf_rn(x2, p, 4.89352455891786e-03f);
    float num = __fmul_rn(xc, p);
    float q = __fmaf_rn(x2, 1.19825839466702e-06f, 1.18534705686654e-04f);
    q = __fmaf_rn(x2, q, 2.26843463243900e-03f);
    q = __fmaf_rn(x2, q, 4.89352518554385e-03f);
    float r = __fdiv_rn(num, q);
    return (fabsf(x) < 0.0004f) ? x : r;
}

__device__ __forceinline__ float xla_logistic_f32(float x) {
    float t = xla_tanh_f32(__fmul_rn(0.5f, x));
    return __fadd_rn(0.5f, __fmul_rn(0.5f, t));
}

__device__ __forceinline__ float ref_adj_key(float simf, int i, int j,
                                             float lamk, float omlk, float temp) {
    float px = g_pos[2 * i], py = g_pos[2 * i + 1];
    float qx = g_pos[2 * j], qy = g_pos[2 * j + 1];
    float sqa = __fadd_rn(__fmul_rn(px, px), __fmul_rn(py, py));
    float sqb = __fadd_rn(__fmul_rn(qx, qx), __fmul_rn(qy, qy));
    float P = __fmaf_rn(py, qy, __fmul_rn(px, qx));
    float S = __fadd_rn(sqa, sqb);
    float d2 = __fadd_rn(S, -(2.0f * P));
    d2 = fmaxf(d2, 0.0f);
    float arg = -__fdiv_rn(d2, 5000.0f);
    float sp = (float)exp((double)arg);     // correctly-rounded fp32 exp
    float comb = __fadd_rn(__fmul_rn(lamk, simf), __fmul_rn(omlk, sp));
    float z = __fmul_rn(comb, temp);
    return xla_logistic_f32(z);
}

// ---------------------------------------------------------------------------
// Kernel 1: row-normalize (fp64 norm) + bf16 quantization of normalized feats.
// ---------------------------------------------------------------------------
__global__ void prep_kernel(const float* __restrict__ feat,
                            const float* __restrict__ pos,
                            const float* __restrict__ lamw,
                            const float* __restrict__ temp) {
    int gwarp = (blockIdx.x * blockDim.x + threadIdx.x) >> 5;
    int lane = threadIdx.x & 31;
    if (gwarp >= NN) return;
    const float* src = feat + (size_t)gwarp * DD;

    double ss = 0.0;
#pragma unroll
    for (int j = lane; j < DD; j += 32) {
        double v = (double)src[j];
        ss += v * v;
    }
#pragma unroll
    for (int off = 16; off > 0; off >>= 1)
        ss += __shfl_down_sync(0xFFFFFFFFu, ss, off);
    ss = __shfl_sync(0xFFFFFFFFu, ss, 0);

    float nrm = fmaxf((float)sqrt(ss), 1e-12f);
    size_t base = (size_t)gwarp * DD;
#pragma unroll
    for (int j = lane; j < DD; j += 32) {
        float v = __fdiv_rn(src[j], nrm);
        g_featn[base + j] = v;
        g_sp0[base + j] = __float2bfloat16_rn(v);
    }

    if (lane < 2) g_pos[2 * gwarp + lane] = pos[2 * gwarp + lane];
    if (gwarp == 0 && lane == 0) {
        float lam = sigmoid_f(*lamw);
        g_lam = lam;
        g_one_m_lam = 1.0f - lam;
        g_temp = *temp;
        float lamk = xla_logistic_f32(*lamw);   // reference's lam
        g_lam_key = lamk;
        g_oml_key = __fadd_rn(1.0f, -lamk);
    }
}

// ---------------------------------------------------------------------------
// Kernel 2: mma.sync bf16 SINGLE-product GEMM (b0*b0'). Noise rms ~1.5e-5 in
// adj units; boundary decisions delegated to the TAU=1.5e-4 refinement band.
// 512 threads, cp.async double buffer (32 KB stages), ldmatrix feed.
// ---------------------------------------------------------------------------
#define NTILE (NN / 128)                   // 64
#define NPAIRS (NTILE * (NTILE + 1) / 2)   // 2080
#define STAGE 32768                        // one buffer: A0 16 KB + B0 16 KB
#define DYN_SMEM 66048                     // max(2*STAGE, 128*129*4)
#define GT 512                             // GEMM threads

// stage one 64-col k-chunk into buffer `base` (swizzled, coalesced)
__device__ __forceinline__ void stage_chunk(unsigned int base, int m0, int n0,
                                            int k0, int tid) {
#pragma unroll
    for (int it = 0; it < 4; it++) {
        int u = it * GT + tid;         // 0..2047
        int mat = u >> 10;             // 0:A0 1:B0
        int idx = u & 1023;
        int row = idx >> 3;
        int grp = idx & 7;
        int grow = ((mat == 0) ? m0 : n0) + row;
        const void* src = (const void*)(g_sp0 + (size_t)grow * DD + k0 + grp * 8);
        unsigned int dst = base + (unsigned)(mat * 16384 + row * 128 +
                                             ((grp ^ (row & 7)) << 4));
        CP_ASYNC16(dst, src);
    }
}

__global__ __launch_bounds__(GT, 1)
void adj_gemm_mma(const float* __restrict__ pos, float* __restrict__ outp) {
    extern __shared__ char dyn[];
    __shared__ float s_qx[128], s_qy[128], s_sqb[128];

    // decode linear tile id -> (bi, bj), bj >= bi
    int t = blockIdx.x;
    int bi = (int)((2.0 * NTILE + 1.0 -
                    sqrt((2.0 * NTILE + 1.0) * (2.0 * NTILE + 1.0) - 8.0 * (double)t)) * 0.5);
    while ((bi + 1) * NTILE - ((bi + 1) * bi) / 2 <= t) bi++;
    while (bi * NTILE - (bi * (bi - 1)) / 2 > t) bi--;
    int bj = bi + (t - (bi * NTILE - (bi * (bi - 1)) / 2));

    const int m0 = bi * 128, n0 = bj * 128;
    const int tid = threadIdx.x;
    const int wid = tid >> 5;
    const int lane = tid & 31;
    const int gid = lane >> 2;
    const int tig = lane & 3;
    const int lane7 = lane & 7;

    const int wm = (wid >> 2) * 32;   // warp m-offset (0,32,64,96)
    const int wn = (wid & 3) * 32;    // warp n-offset (0,32,64,96)

    // ldmatrix per-lane row/group selectors
    const int ra  = wm + ((lane & 8) ? 8 : 0) + lane7;     // A row (per mi +16)
    const int gsa = (lane >> 4) & 1;                       // A kgroup select
    const int rb  = wn + ((lane & 16) ? 8 : 0) + lane7;    // B row (per pair +16)
    const int gsb = (lane >> 3) & 1;                       // B kgroup select

    const unsigned int sbase = smem_u32(dyn);

    if (tid < 128) {
        int n = n0 + tid;
        float qx = pos[2 * n], qy = pos[2 * n + 1];
        s_qx[tid] = qx; s_qy[tid] = qy;
        s_sqb[tid] = __fadd_rn(__fmul_rn(qx, qx), __fmul_rn(qy, qy));
    }

    float d[2][4][4];
#pragma unroll
    for (int mi = 0; mi < 2; mi++)
#pragma unroll
        for (int ni = 0; ni < 4; ni++)
#pragma unroll
            for (int r = 0; r < 4; r++) d[mi][ni][r] = 0.0f;

    stage_chunk(sbase, m0, n0, 0, tid);
    CP_COMMIT();

#pragma unroll 1
    for (int ch = 0; ch < 8; ch++) {
        CP_WAIT0();            // current chunk's data landed (this thread)
        __syncthreads();       // all threads landed + prev buffer drained
        if (ch < 7) {          // overlap next stage with current compute
            stage_chunk(sbase + ((ch + 1) & 1) * STAGE, m0, n0, (ch + 1) * 64, tid);
            CP_COMMIT();
        }

        const unsigned int buf = sbase + (ch & 1) * STAGE;
#pragma unroll
        for (int ks = 0; ks < 4; ks++) {
            const unsigned int swa = (unsigned)(((ks * 2 + gsa) ^ lane7) << 4);
            const unsigned int swb = (unsigned)(((ks * 2 + gsb) ^ lane7) << 4);
            unsigned int a[2][4], b[2][4];
#pragma unroll
            for (int mi = 0; mi < 2; mi++) {
                unsigned int ad = buf + (unsigned)((ra + mi * 16) * 128) + swa;
                LDSM_X4(a[mi], ad);
            }
#pragma unroll
            for (int p = 0; p < 2; p++) {
                unsigned int bd = buf + (unsigned)(16384 +
                                    (rb + p * 16) * 128) + swb;
                LDSM_X4(b[p], bd);
            }
#pragma unroll
            for (int mi = 0; mi < 2; mi++)
#pragma unroll
                for (int ni = 0; ni < 4; ni++) {
                    const int p = ni >> 1, o = (ni & 1) * 2;
                    MMA16816(d[mi][ni], a[mi], b[p][o], b[p][o + 1]);
                }
        }
    }
    __syncthreads();   // all warps done with LDSM before smem_t overlay

    // ---- epilogue in registers -> padded smem (exact validated fp ops) ----
    float* smem_t = (float*)dyn;   // 128 x 129 floats (staging done)
    const float lam = g_lam, oml = g_one_m_lam, temp = g_temp;
#pragma unroll
    for (int mi = 0; mi < 2; mi++) {
#pragma unroll
        for (int rh = 0; rh < 2; rh++) {
            int lr = wm + mi * 16 + gid + rh * 8;
            int m = m0 + lr;
            float px = pos[2 * m], py = pos[2 * m + 1];
            float sqa = __fadd_rn(__fmul_rn(px, px), __fmul_rn(py, py));
#pragma unroll
            for (int ni = 0; ni < 4; ni++) {
#pragma unroll
                for (int cc = 0; cc < 2; cc++) {
                    int lc = wn + ni * 8 + 2 * tig + cc;
                    float sim = d[mi][ni][rh * 2 + cc];
                    float qx = s_qx[lc], qy = s_qy[lc];
                    float P = __fmaf_rn(py, qy, __fmul_rn(px, qx));
                    float S = __fadd_rn(sqa, s_sqb[lc]);
                    float d2 = __fadd_rn(S, -(2.0f * P));
                    d2 = fmaxf(d2, 0.0f);
                    float sp = expf(-__fdiv_rn(d2, 5000.0f));
                    float comb = __fadd_rn(__fmul_rn(lam, sim),
                                           __fmul_rn(oml, sp));
                    smem_t[lr * 129 + lc] = sigmoid_f(__fmul_rn(comb, temp));
                }
            }
        }
    }
    __syncthreads();

    // ---- stores: normal rows + mirrored rows (conflict-free, stride 129) ----
    const bool diag = (bi == bj);
#pragma unroll 1
    for (int rr = 0; rr < 8; rr++) {
        int r = wid * 8 + rr;
        float* orow = outp + (size_t)(m0 + r) * NN + n0;
#pragma unroll
        for (int c = lane; c < 128; c += 32)
            orow[c] = smem_t[r * 129 + c];
        if (!diag) {
            float* mrow = outp + (size_t)(n0 + r) * NN + m0;
#pragma unroll
            for (int c2 = lane; c2 < 128; c2 += 32)
                mrow[c2] = smem_t[c2 * 129 + r];
        }
    }
}

// ---------------------------------------------------------------------------
// Kernel 3: per-row exact top-k IN PLACE + boundary-band refinement with
// reference-replica keys. TAU widened to 1.5e-4 (10 sigma of 1-product GEMM
// noise); refinement machinery identical to the validated version.
// ---------------------------------------------------------------------------
#define TAU 1.5e-4f
#define MAXBAND 128
#define KT 512

__global__ void topk_kernel(float* __restrict__ out,
                            const int* __restrict__ kptr,
                            long long out_size) {
    const int row = blockIdx.x;
    const int tid = threadIdx.x;
    const int NT = KT;
    const int lane = tid & 31;

    __shared__ int cnt[256];
    __shared__ int wsum[8];
    __shared__ unsigned int sh_pfx;
    __shared__ int sh_rem;
    __shared__ int sh_nabove, sh_bandcnt;
    __shared__ int bandidx[MAXBAND];
    __shared__ unsigned int bandkey[MAXBAND];
    __shared__ unsigned char bandkeep[MAXBAND];
    __shared__ double red_d[KT];
    extern __shared__ unsigned int srow[];   // NN uint32

    const int k = *kptr;
    const unsigned int* arow =
        (const unsigned int*)(out + (size_t)row * NN);
    for (int j = tid; j < NN; j += NT) srow[j] = arow[j];
    if (tid == 0) { sh_pfx = 0u; sh_rem = k; sh_nabove = 0; sh_bandcnt = 0; }
    __syncthreads();

#pragma unroll 1
    for (int pass = 0; pass < 4; pass++) {
        int shift = 24 - 8 * pass;
        unsigned int hi_mask = (pass == 0) ? 0u : (0xFFFFFFFFu << (shift + 8));
        if (tid < 256) cnt[tid] = 0;
        __syncthreads();
        unsigned int pfx = sh_pfx;
        for (int j = tid; j < NN; j += NT) {
            unsigned int v = srow[j];
            bool act = ((v & hi_mask) == pfx);
            unsigned int bin = (v >> shift) & 255;
            unsigned int bal = __ballot_sync(0xFFFFFFFFu, act);
            if (act) {
                unsigned int peers = __match_any_sync(bal, bin);
                int leader = __ffs(peers) - 1;
                if (lane == leader)
                    atomicAdd(&cnt[bin], __popc(peers));
            }
        }
        __syncthreads();
        if (tid < 256) {
            int wv = cnt[tid];
#pragma unroll
            for (int off = 16; off > 0; off >>= 1)
                wv += __shfl_down_sync(0xFFFFFFFFu, wv, off);
            if (lane == 0) wsum[tid >> 5] = wv;
        }
        __syncthreads();
        if (tid == 0) {
            int rem = sh_rem;
            int w = 7;
            for (; w > 0; w--) {
                if (rem - wsum[w] <= 0) break;
                rem -= wsum[w];
            }
            int b = w * 32 + 31;
            for (; b > w * 32; b--) {
                if (rem - cnt[b] <= 0) break;
                rem -= cnt[b];
            }
            sh_pfx = pfx | ((unsigned int)b << shift);
            sh_rem = rem;
        }
        __syncthreads();
    }

    const float Tf = __uint_as_float(sh_pfx);
    const float band_hi = Tf + TAU;
    const float band_lo = Tf - TAU;

    for (int j = tid; j < NN; j += NT) {
        float v = __uint_as_float(srow[j]);
        if (v > band_hi) {
            atomicAdd(&sh_nabove, 1);
        } else if (v >= band_lo) {
            int p = atomicAdd(&sh_bandcnt, 1);
            if (p < MAXBAND) bandidx[p] = j;
        }
    }
    __syncthreads();

    const int n_above = sh_nabove;
    const int band_cnt_raw = sh_bandcnt;
    const int band_cnt = min(band_cnt_raw, MAXBAND);
    const int need = k - n_above;     // >= 1 always

    bool refined = false;
    if (band_cnt_raw <= MAXBAND && band_cnt_raw > need) {
        refined = true;
        const float lamk = g_lam_key, omlk = g_oml_key, temp = g_temp;
        const float* fa = &g_featn[(size_t)row * DD];

        for (int c = 0; c < band_cnt; c++) {
            int j = bandidx[c];
            const float* fb = &g_featn[(size_t)j * DD];
            double part = 0.0;
            for (int t = tid; t < DD; t += NT)
                part += (double)fa[t] * (double)fb[t];
            red_d[tid] = part;
            __syncthreads();
            for (int s = KT / 2; s > 0; s >>= 1) {
                if (tid < s) red_d[tid] += red_d[tid + s];
                __syncthreads();
            }
            if (tid == 0) {
                float simf = (float)red_d[0];   // correctly-rounded fp32 sim
                float a = ref_adj_key(simf, row, j, lamk, omlk, temp);
                bandkey[c] = __float_as_uint(a);
                bandkeep[c] = 0;
            }
            __syncthreads();
        }
        if (tid == 0) {
            for (int pick = 0; pick < need; pick++) {
                int best = -1;
                for (int c = 0; c < band_cnt; c++) {
                    if (bandkeep[c]) continue;
                    if (best < 0 ||
                        bandkey[c] > bandkey[best] ||
                        (bandkey[c] == bandkey[best] && bandidx[c] < bandidx[best]))
                        best = c;
                }
                bandkeep[best] = 1;
            }
        }
        __syncthreads();
    }

    float* orow = out + (size_t)row * NN;
    const unsigned int Tkey = sh_pfx;
    for (int j = tid; j < NN; j += NT) {
        unsigned int vb = srow[j];
        float v = __uint_as_float(vb);
        float o = 0.0f;
        if (v > band_hi) {
            o = v;
        } else if (v >= band_lo) {
            if (!refined) {
                if (band_cnt_raw <= MAXBAND) {
                    o = v;                       // band_cnt == need: keep all
                } else {
                    o = (vb >= Tkey) ? v : 0.0f; // overflow fallback
                }
            } else {
                for (int c = 0; c < band_cnt; c++) {
                    if (bandidx[c] == j) { o = bandkeep[c] ? v : 0.0f; break; }
                }
            }
        }
        orow[j] = o;
    }

    if (row == 0 && tid == 0 && out_size > (long long)NN * NN)
        out[(size_t)NN * NN] = g_lam;    // second tuple output: lam scalar
}

// ---------------------------------------------------------------------------
extern "C" void kernel_launch(void* const* d_in, const int* in_sizes, int n_in,
                              void* d_out, int out_size) {
    const float* feat = (const float*)d_in[0];   // (8192, 512)
    const float* pos  = (const float*)d_in[1];   // (8192, 2)
    const float* lamw = (const float*)d_in[2];   // scalar
    const float* temp = (const float*)d_in[3];   // scalar
    const int*   kptr = (const int*)d_in[4];     // scalar int
    float* out = (float*)d_out;

    cudaFuncSetAttribute(adj_gemm_mma,
                         cudaFuncAttributeMaxDynamicSharedMemorySize, DYN_SMEM);

    prep_kernel<<<NN / 8, 256>>>(feat, pos, lamw, temp);
    adj_gemm_mma<<<NPAIRS, GT, DYN_SMEM>>>(pos, out);
    topk_kernel<<<NN, KT, NN * sizeof(unsigned int)>>>(out, kptr,
                                                       (long long)out_size);
}

// round 15
// speedup vs baseline: 3.2483x; 1.0577x over previous
#include <cuda_runtime.h>
#include <cuda_bf16.h>
#include <math.h>

#define NN 8192
#define DD 512

// Scratch (static device globals — no runtime allocation allowed)
__device__ float g_featn[(size_t)NN * DD];                     // normalized feats
__device__ __align__(16) __nv_bfloat16 g_sp0[(size_t)NN * DD]; // bf16 of featn
__device__ float g_pos[(size_t)NN * 2];
__device__ float g_lam, g_one_m_lam, g_temp;        // exp-form (output values)
__device__ float g_lam_key, g_oml_key;              // XLA tanh-form (ranking keys)

// m16n8k16 bf16 MMA, fp32 accumulate (plain PTX, valid on sm_103)
#define MMA16816(d, a, b0v, b1v)                                              \
    asm volatile(                                                             \
        "mma.sync.aligned.m16n8k16.row.col.f32.bf16.bf16.f32 "                \
        "{%0,%1,%2,%3}, {%4,%5,%6,%7}, {%8,%9}, {%0,%1,%2,%3};"               \
        : "+f"((d)[0]), "+f"((d)[1]), "+f"((d)[2]), "+f"((d)[3])              \
        : "r"((a)[0]), "r"((a)[1]), "r"((a)[2]), "r"((a)[3]),                 \
          "r"(b0v), "r"(b1v))

#define LDSM_X4(r, addr)                                                      \
    asm volatile("ldmatrix.sync.aligned.m8n8.x4.shared.b16 {%0,%1,%2,%3}, [%4];" \
        : "=r"((r)[0]), "=r"((r)[1]), "=r"((r)[2]), "=r"((r)[3]) : "r"(addr))

#define CP_ASYNC16(dst, src)                                                  \
    asm volatile("cp.async.ca.shared.global [%0], [%1], 16;" :: "r"(dst), "l"(src))
#define CP_COMMIT() asm volatile("cp.async.commit_group;" ::: "memory")
#define CP_WAIT0()  asm volatile("cp.async.wait_group 0;" ::: "memory")

__device__ __forceinline__ unsigned int smem_u32(const void* p) {
    return (unsigned int)__cvta_generic_to_shared(p);
}

// ---------------------------------------------------------------------------
// Numerics helpers (validated rounds 1-6 — DO NOT CHANGE)
// ---------------------------------------------------------------------------
__device__ __forceinline__ float sigmoid_f(float x) {
    if (x >= 0.0f) {
        float e = expf(-x);
        return __fdiv_rn(1.0f, __fadd_rn(1.0f, e));
    } else {
        float e = expf(x);
        return __fdiv_rn(e, __fadd_rn(1.0f, e));
    }
}

__device__ __forceinline__ float xla_tanh_f32(float x) {
    const float kClamp = 7.90531110763549805f;
    float xc = fminf(fmaxf(x, -kClamp), kClamp);
    float x2 = __fmul_rn(xc, xc);
    float p = __fmaf_rn(x2, -2.76076847742355e-16f, 2.00018790482477e-13f);
    p = __fmaf_rn(x2, p, -8.60467152213735e-11f);
    p = __fmaf_rn(x2, p, 5.12229709037114e-08f);
    p = __fmaf_rn(x2, p, 1.48572235717979e-05f);
    p = __fmaf_rn(x2, p, 6.37261928875436e-04f);
    p = __fmaf_rn(x2, p, 4.89352455891786e-03f);
    float num = __fmul_rn(xc, p);
    float q = __fmaf_rn(x2, 1.19825839466702e-06f, 1.18534705686654e-04f);
    q = __fmaf_rn(x2, q, 2.26843463243900e-03f);
    q = __fmaf_rn(x2, q, 4.89352518554385e-03f);
    float r = __fdiv_rn(num, q);
    return (fabsf(x) < 0.0004f) ? x : r;
}

__device__ __forceinline__ float xla_logistic_f32(float x) {
    float t = xla_tanh_f32(__fmul_rn(0.5f, x));
    return __fadd_rn(0.5f, __fmul_rn(0.5f, t));
}

__device__ __forceinline__ float ref_adj_key(float simf, int i, int j,
                                             float lamk, float omlk, float temp) {
    float px = g_pos[2 * i], py = g_pos[2 * i + 1];
    float qx = g_pos[2 * j], qy = g_pos[2 * j + 1];
    float sqa = __fadd_rn(__fmul_rn(px, px), __fmul_rn(py, py));
    float sqb = __fadd_rn(__fmul_rn(qx, qx), __fmul_rn(qy, qy));
    float P = __fmaf_rn(py, qy, __fmul_rn(px, qx));
    float S = __fadd_rn(sqa, sqb);
    float d2 = __fadd_rn(S, -(2.0f * P));
    d2 = fmaxf(d2, 0.0f);
    float arg = -__fdiv_rn(d2, 5000.0f);
    float sp = (float)exp((double)arg);     // correctly-rounded fp32 exp
    float comb = __fadd_rn(__fmul_rn(lamk, simf), __fmul_rn(omlk, sp));
    float z = __fmul_rn(comb, temp);
    return xla_logistic_f32(z);
}

// ---------------------------------------------------------------------------
// Kernel 1: row-normalize (fp64 norm) + bf16 quantization of normalized feats.
// ---------------------------------------------------------------------------
__global__ void prep_kernel(const float* __restrict__ feat,
                            const float* __restrict__ pos,
                            const float* __restrict__ lamw,
                            const float* __restrict__ temp) {
    int gwarp = (blockIdx.x * blockDim.x + threadIdx.x) >> 5;
    int lane = threadIdx.x & 31;
    if (gwarp >= NN) return;
    const float* src = feat + (size_t)gwarp * DD;

    double ss = 0.0;
#pragma unroll
    for (int j = lane; j < DD; j += 32) {
        double v = (double)src[j];
        ss += v * v;
    }
#pragma unroll
    for (int off = 16; off > 0; off >>= 1)
        ss += __shfl_down_sync(0xFFFFFFFFu, ss, off);
    ss = __shfl_sync(0xFFFFFFFFu, ss, 0);

    float nrm = fmaxf((float)sqrt(ss), 1e-12f);
    size_t base = (size_t)gwarp * DD;
#pragma unroll
    for (int j = lane; j < DD; j += 32) {
        float v = __fdiv_rn(src[j], nrm);
        g_featn[base + j] = v;
        g_sp0[base + j] = __float2bfloat16_rn(v);
    }

    if (lane < 2) g_pos[2 * gwarp + lane] = pos[2 * gwarp + lane];
    if (gwarp == 0 && lane == 0) {
        float lam = sigmoid_f(*lamw);
        g_lam = lam;
        g_one_m_lam = 1.0f - lam;
        g_temp = *temp;
        float lamk = xla_logistic_f32(*lamw);   // reference's lam
        g_lam_key = lamk;
        g_oml_key = __fadd_rn(1.0f, -lamk);
    }
}

// ---------------------------------------------------------------------------
// Kernel 2: mma.sync bf16 SINGLE-product GEMM (b0*b0'). Noise rms ~1.5e-5 in
// adj units; boundary decisions delegated to the TAU=1.5e-4 refinement band.
// 512 threads, cp.async double buffer (32 KB stages), ldmatrix feed.
// ---------------------------------------------------------------------------
#define NTILE (NN / 128)                   // 64
#define NPAIRS (NTILE * (NTILE + 1) / 2)   // 2080
#define STAGE 32768                        // one buffer: A0 16 KB + B0 16 KB
#define DYN_SMEM 66048                     // max(2*STAGE, 128*129*4)
#define GT 512                             // GEMM threads

// stage one 64-col k-chunk into buffer `base` (swizzled, coalesced)
__device__ __forceinline__ void stage_chunk(unsigned int base, int m0, int n0,
                                            int k0, int tid) {
#pragma unroll
    for (int it = 0; it < 4; it++) {
        int u = it * GT + tid;         // 0..2047
        int mat = u >> 10;             // 0:A0 1:B0
        int idx = u & 1023;
        int row = idx >> 3;
        int grp = idx & 7;
        int grow = ((mat == 0) ? m0 : n0) + row;
        const void* src = (const void*)(g_sp0 + (size_t)grow * DD + k0 + grp * 8);
        unsigned int dst = base + (unsigned)(mat * 16384 + row * 128 +
                                             ((grp ^ (row & 7)) << 4));
        CP_ASYNC16(dst, src);
    }
}

__global__ __launch_bounds__(GT, 1)
void adj_gemm_mma(const float* __restrict__ pos, float* __restrict__ outp) {
    extern __shared__ char dyn[];
    __shared__ float s_qx[128], s_qy[128], s_sqb[128];

    // decode linear tile id -> (bi, bj), bj >= bi
    int t = blockIdx.x;
    int bi = (int)((2.0 * NTILE + 1.0 -
                    sqrt((2.0 * NTILE + 1.0) * (2.0 * NTILE + 1.0) - 8.0 * (double)t)) * 0.5);
    while ((bi + 1) * NTILE - ((bi + 1) * bi) / 2 <= t) bi++;
    while (bi * NTILE - (bi * (bi - 1)) / 2 > t) bi--;
    int bj = bi + (t - (bi * NTILE - (bi * (bi - 1)) / 2));

    const int m0 = bi * 128, n0 = bj * 128;
    const int tid = threadIdx.x;
    const int wid = tid >> 5;
    const int lane = tid & 31;
    const int gid = lane >> 2;
    const int tig = lane & 3;
    const int lane7 = lane & 7;

    const int wm = (wid >> 2) * 32;   // warp m-offset (0,32,64,96)
    const int wn = (wid & 3) * 32;    // warp n-offset (0,32,64,96)

    // ldmatrix per-lane row/group selectors
    const int ra  = wm + ((lane & 8) ? 8 : 0) + lane7;     // A row (per mi +16)
    const int gsa = (lane >> 4) & 1;                       // A kgroup select
    const int rb  = wn + ((lane & 16) ? 8 : 0) + lane7;    // B row (per pair +16)
    const int gsb = (lane >> 3) & 1;                       // B kgroup select

    const unsigned int sbase = smem_u32(dyn);

    if (tid < 128) {
        int n = n0 + tid;
        float qx = pos[2 * n], qy = pos[2 * n + 1];
        s_qx[tid] = qx; s_qy[tid] = qy;
        s_sqb[tid] = __fadd_rn(__fmul_rn(qx, qx), __fmul_rn(qy, qy));
    }

    float d[2][4][4];
#pragma unroll
    for (int mi = 0; mi < 2; mi++)
#pragma unroll
        for (int ni = 0; ni < 4; ni++)
#pragma unroll
            for (int r = 0; r < 4; r++) d[mi][ni][r] = 0.0f;

    stage_chunk(sbase, m0, n0, 0, tid);
    CP_COMMIT();

#pragma unroll 1
    for (int ch = 0; ch < 8; ch++) {
        CP_WAIT0();            // current chunk's data landed (this thread)
        __syncthreads();       // all threads landed + prev buffer drained
        if (ch < 7) {          // overlap next stage with current compute
            stage_chunk(sbase + ((ch + 1) & 1) * STAGE, m0, n0, (ch + 1) * 64, tid);
            CP_COMMIT();
        }

        const unsigned int buf = sbase + (ch & 1) * STAGE;
#pragma unroll
        for (int ks = 0; ks < 4; ks++) {
            const unsigned int swa = (unsigned)(((ks * 2 + gsa) ^ lane7) << 4);
            const unsigned int swb = (unsigned)(((ks * 2 + gsb) ^ lane7) << 4);
            unsigned int a[2][4], b[2][4];
#pragma unroll
            for (int mi = 0; mi < 2; mi++) {
                unsigned int ad = buf + (unsigned)((ra + mi * 16) * 128) + swa;
                LDSM_X4(a[mi], ad);
            }
#pragma unroll
            for (int p = 0; p < 2; p++) {
                unsigned int bd = buf + (unsigned)(16384 +
                                    (rb + p * 16) * 128) + swb;
                LDSM_X4(b[p], bd);
            }
#pragma unroll
            for (int mi = 0; mi < 2; mi++)
#pragma unroll
                for (int ni = 0; ni < 4; ni++) {
                    const int p = ni >> 1, o = (ni & 1) * 2;
                    MMA16816(d[mi][ni], a[mi], b[p][o], b[p][o + 1]);
                }
        }
    }
    __syncthreads();   // all warps done with LDSM before smem_t overlay

    // ---- epilogue in registers -> padded smem (exact validated fp ops) ----
    float* smem_t = (float*)dyn;   // 128 x 129 floats (staging done)
    const float lam = g_lam, oml = g_one_m_lam, temp = g_temp;
#pragma unroll
    for (int mi = 0; mi < 2; mi++) {
#pragma unroll
        for (int rh = 0; rh < 2; rh++) {
            int lr = wm + mi * 16 + gid + rh * 8;
            int m = m0 + lr;
            float px = pos[2 * m], py = pos[2 * m + 1];
            float sqa = __fadd_rn(__fmul_rn(px, px), __fmul_rn(py, py));
#pragma unroll
            for (int ni = 0; ni < 4; ni++) {
#pragma unroll
                for (int cc = 0; cc < 2; cc++) {
                    int lc = wn + ni * 8 + 2 * tig + cc;
                    float sim = d[mi][ni][rh * 2 + cc];
                    float qx = s_qx[lc], qy = s_qy[lc];
                    float P = __fmaf_rn(py, qy, __fmul_rn(px, qx));
                    float S = __fadd_rn(sqa, s_sqb[lc]);
                    float d2 = __fadd_rn(S, -(2.0f * P));
                    d2 = fmaxf(d2, 0.0f);
                    float sp = expf(-__fdiv_rn(d2, 5000.0f));
                    float comb = __fadd_rn(__fmul_rn(lam, sim),
                                           __fmul_rn(oml, sp));
                    smem_t[lr * 129 + lc] = sigmoid_f(__fmul_rn(comb, temp));
                }
            }
        }
    }
    __syncthreads();

    // ---- stores: normal rows + mirrored rows (conflict-free, stride 129) ----
    const bool diag = (bi == bj);
#pragma unroll 1
    for (int rr = 0; rr < 8; rr++) {
        int r = wid * 8 + rr;
        float* orow = outp + (size_t)(m0 + r) * NN + n0;
#pragma unroll
        for (int c = lane; c < 128; c += 32)
            orow[c] = smem_t[r * 129 + c];
        if (!diag) {
            float* mrow = outp + (size_t)(n0 + r) * NN + m0;
#pragma unroll
            for (int c2 = lane; c2 < 128; c2 += 32)
                mrow[c2] = smem_t[c2 * 129 + r];
        }
    }
}

// ---------------------------------------------------------------------------
// Kernel 3: per-row exact top-k IN PLACE + boundary-band refinement with
// reference-replica keys. Refinement is WARP-PER-CANDIDATE (lane-strided
// fp64 dot + shuffle reduce, no barriers inside) — all candidates in
// parallel across 16 warps. Key = fp32(fp64 dot) -> summation-order change
// is immaterial at fp32 rounding granularity. Selection/ties unchanged.
// ---------------------------------------------------------------------------
#define TAU 1.5e-4f
#define MAXBAND 128
#define KT 512

__global__ void topk_kernel(float* __restrict__ out,
                            const int* __restrict__ kptr,
                            long long out_size) {
    const int row = blockIdx.x;
    const int tid = threadIdx.x;
    const int NT = KT;
    const int lane = tid & 31;
    const int wid = tid >> 5;

    __shared__ int cnt[256];
    __shared__ int wsum[8];
    __shared__ unsigned int sh_pfx;
    __shared__ int sh_rem;
    __shared__ int sh_nabove, sh_bandcnt;
    __shared__ int bandidx[MAXBAND];
    __shared__ unsigned int bandkey[MAXBAND];
    __shared__ unsigned char bandkeep[MAXBAND];
    extern __shared__ unsigned int srow[];   // NN uint32

    const int k = *kptr;
    const unsigned int* arow =
        (const unsigned int*)(out + (size_t)row * NN);
    for (int j = tid; j < NN; j += NT) srow[j] = arow[j];
    if (tid == 0) { sh_pfx = 0u; sh_rem = k; sh_nabove = 0; sh_bandcnt = 0; }
    __syncthreads();

#pragma unroll 1
    for (int pass = 0; pass < 4; pass++) {
        int shift = 24 - 8 * pass;
        unsigned int hi_mask = (pass == 0) ? 0u : (0xFFFFFFFFu << (shift + 8));
        if (tid < 256) cnt[tid] = 0;
        __syncthreads();
        unsigned int pfx = sh_pfx;
        for (int j = tid; j < NN; j += NT) {
            unsigned int v = srow[j];
            bool act = ((v & hi_mask) == pfx);
            unsigned int bin = (v >> shift) & 255;
            unsigned int bal = __ballot_sync(0xFFFFFFFFu, act);
            if (act) {
                unsigned int peers = __match_any_sync(bal, bin);
                int leader = __ffs(peers) - 1;
                if (lane == leader)
                    atomicAdd(&cnt[bin], __popc(peers));
            }
        }
        __syncthreads();
        if (tid < 256) {
            int wv = cnt[tid];
#pragma unroll
            for (int off = 16; off > 0; off >>= 1)
                wv += __shfl_down_sync(0xFFFFFFFFu, wv, off);
            if (lane == 0) wsum[tid >> 5] = wv;
        }
        __syncthreads();
        if (tid == 0) {
            int rem = sh_rem;
            int w = 7;
            for (; w > 0; w--) {
                if (rem - wsum[w] <= 0) break;
                rem -= wsum[w];
            }
            int b = w * 32 + 31;
            for (; b > w * 32; b--) {
                if (rem - cnt[b] <= 0) break;
                rem -= cnt[b];
            }
            sh_pfx = pfx | ((unsigned int)b << shift);
            sh_rem = rem;
        }
        __syncthreads();
    }

    const float Tf = __uint_as_float(sh_pfx);
    const float band_hi = Tf + TAU;
    const float band_lo = Tf - TAU;

    for (int j = tid; j < NN; j += NT) {
        float v = __uint_as_float(srow[j]);
        if (v > band_hi) {
            atomicAdd(&sh_nabove, 1);
        } else if (v >= band_lo) {
            int p = atomicAdd(&sh_bandcnt, 1);
            if (p < MAXBAND) bandidx[p] = j;
        }
    }
    __syncthreads();

    const int n_above = sh_nabove;
    const int band_cnt_raw = sh_bandcnt;
    const int band_cnt = min(band_cnt_raw, MAXBAND);
    const int need = k - n_above;     // >= 1 always

    bool refined = false;
    if (band_cnt_raw <= MAXBAND && band_cnt_raw > need) {
        refined = true;
        const float lamk = g_lam_key, omlk = g_oml_key, temp = g_temp;
        const float* fa = &g_featn[(size_t)row * DD];

        // warp-per-candidate: warp w handles candidates w, w+16, ...
        for (int c = wid; c < band_cnt; c += 16) {
            int j = bandidx[c];
            const float* fb = &g_featn[(size_t)j * DD];
            double part = 0.0;
#pragma unroll
            for (int t2 = lane; t2 < DD; t2 += 32)
                part += (double)fa[t2] * (double)fb[t2];
#pragma unroll
            for (int off = 16; off > 0; off >>= 1)
                part += __shfl_down_sync(0xFFFFFFFFu, part, off);
            if (lane == 0) {
                float simf = (float)part;       // correctly-rounded fp32 sim
                float a = ref_adj_key(simf, row, j, lamk, omlk, temp);
                bandkey[c] = __float_as_uint(a);
                bandkeep[c] = 0;
            }
        }
        __syncthreads();

        if (tid == 0) {
            for (int pick = 0; pick < need; pick++) {
                int best = -1;
                for (int c = 0; c < band_cnt; c++) {
                    if (bandkeep[c]) continue;
                    if (best < 0 ||
                        bandkey[c] > bandkey[best] ||
                        (bandkey[c] == bandkey[best] && bandidx[c] < bandidx[best]))
                        best = c;
                }
                bandkeep[best] = 1;
            }
        }
        __syncthreads();
    }

    float* orow = out + (size_t)row * NN;
    const unsigned int Tkey = sh_pfx;
    for (int j = tid; j < NN; j += NT) {
        unsigned int vb = srow[j];
        float v = __uint_as_float(vb);
        float o = 0.0f;
        if (v > band_hi) {
            o = v;
        } else if (v >= band_lo) {
            if (!refined) {
                if (band_cnt_raw <= MAXBAND) {
                    o = v;                       // band_cnt == need: keep all
                } else {
                    o = (vb >= Tkey) ? v : 0.0f; // overflow fallback
                }
            } else {
                for (int c = 0; c < band_cnt; c++) {
                    if (bandidx[c] == j) { o = bandkeep[c] ? v : 0.0f; break; }
                }
            }
        }
        orow[j] = o;
    }

    if (row == 0 && tid == 0 && out_size > (long long)NN * NN)
        out[(size_t)NN * NN] = g_lam;    // second tuple output: lam scalar
}

// ---------------------------------------------------------------------------
extern "C" void kernel_launch(void* const* d_in, const int* in_sizes, int n_in,
                              void* d_out, int out_size) {
    const float* feat = (const float*)d_in[0];   // (8192, 512)
    const float* pos  = (const float*)d_in[1];   // (8192, 2)
    const float* lamw = (const float*)d_in[2];   // scalar
    const float* temp = (const float*)d_in[3];   // scalar
    const int*   kptr = (const int*)d_in[4];     // scalar int
    float* out = (float*)d_out;

    cudaFuncSetAttribute(adj_gemm_mma,
                         cudaFuncAttributeMaxDynamicSharedMemorySize, DYN_SMEM);

    prep_kernel<<<NN / 8, 256>>>(feat, pos, lamw, temp);
    adj_gemm_mma<<<NPAIRS, GT, DYN_SMEM>>>(pos, out);
    topk_kernel<<<NN, KT, NN * sizeof(unsigned int)>>>(out, kptr,
                                                       (long long)out_size);
}